// round 9
// baseline (speedup 1.0000x reference)
#include <cuda_runtime.h>
#include <cuda_bf16.h>
#include <math.h>
#include <stdint.h>

#define NB 32
#define ND 256
#define NTOK 4096
#define NSLOT 8

// ---------------- scratch (device globals; no allocation allowed) ----------------
__device__ uint32_t g_kb[NB * NTOK * 128];     // bf16-pair packed k: 67 MB
__device__ uint32_t g_vb[NB * NTOK * 128];     // bf16-pair packed v: 67 MB
__device__ uint32_t g_wp[4][128 * ND];         // bf16-pair packed weights: w1,w2,k,v
__device__ float g_egT[ND * NTOK];             // transposed enc_g [d][tok]
__device__ float g_ebT[ND * NTOK];             // transposed enc_b [d][tok]
__device__ float g_stats_part[NB * 64 * 2];
__device__ float g_stats[NB * 2];              // mean, rstd per batch
__device__ float g_slots[NB * NSLOT * ND];
__device__ float g_q[NB * NSLOT * ND];
__device__ float g_upd_part[NB * 32 * NSLOT * ND];
__device__ float g_psum_part[NB * 32 * NSLOT];
__device__ float g_upd[NB * NSLOT * ND];
__device__ float g_gi[NB * NSLOT * 768];
__device__ float g_gh[NB * NSLOT * 768];

__device__ __forceinline__ float warp_sum(float v) {
#pragma unroll
    for (int o = 16; o; o >>= 1) v += __shfl_xor_sync(0xffffffffu, v, o);
    return v;
}

__device__ __forceinline__ uint32_t packbf(float a, float b) {
    __nv_bfloat162 h = __floats2bfloat162_rn(a, b);  // .x = a (low), .y = b (high)
    return *(uint32_t*)&h;
}
__device__ __forceinline__ float2 unpackbf(uint32_t u) {
    __nv_bfloat162 h = *(__nv_bfloat162*)&u;
    return __bfloat1622float2(h);
}

// ---------------- K0: per-batch sum / sumsq of h = x + pos (exact fp32) ----------------
__global__ void __launch_bounds__(256) k_stats(const float* __restrict__ x,
                                               const float* __restrict__ pos_w,
                                               const float* __restrict__ pos_b) {
    int b = blockIdx.x, c = blockIdx.y, tid = threadIdx.x;
    float s = 0.f, q = 0.f;
    int base = c * 16384;
    for (int e = base + tid; e < base + 16384; e += 256) {
        int d = e >> 12;
        int ij = e & 4095;
        int ti = ij >> 6, tj = ij & 63;
        float fi = ti * (1.0f / 63.0f), fj = tj * (1.0f / 63.0f);
        float p = fi * pos_w[d] + fj * pos_w[256 + d] + (1.0f - fi) * pos_w[512 + d] +
                  (1.0f - fj) * pos_w[768 + d] + pos_b[d];
        float v = x[b * 1048576 + e] + p;
        s += v;
        q += v * v;
    }
    s = warp_sum(s);
    q = warp_sum(q);
    __shared__ float rs[8], rq[8];
    int w = tid >> 5, lane = tid & 31;
    if (lane == 0) { rs[w] = s; rq[w] = q; }
    __syncthreads();
    if (tid == 0) {
        float S = 0.f, Q = 0.f;
#pragma unroll
        for (int i = 0; i < 8; i++) { S += rs[i]; Q += rq[i]; }
        g_stats_part[(b * 64 + c) * 2 + 0] = S;
        g_stats_part[(b * 64 + c) * 2 + 1] = Q;
    }
}

// ---------------- K0b: finalize per-batch stats (parallel tree in double) ----------------
__global__ void __launch_bounds__(64) k_stats2() {
    __shared__ double rs[64], rq[64];
    int b = blockIdx.x, tid = threadIdx.x;
    rs[tid] = (double)g_stats_part[(b * 64 + tid) * 2 + 0];
    rq[tid] = (double)g_stats_part[(b * 64 + tid) * 2 + 1];
    __syncthreads();
#pragma unroll
    for (int o = 32; o; o >>= 1) {
        if (tid < o) {
            rs[tid] += rs[tid + o];
            rq[tid] += rq[tid + o];
        }
        __syncthreads();
    }
    if (tid == 0) {
        double N = 1048576.0;
        double mu = rs[0] / N;
        double var = rq[0] / N - mu * mu;
        g_stats[b * 2 + 0] = (float)mu;
        g_stats[b * 2 + 1] = (float)(1.0 / sqrt(var + 1e-5));
    }
}

// ---------------- weight pre-pack + enc_g/enc_b transpose (merged) ----------------
__global__ void __launch_bounds__(256) k_cvtW2(const float* __restrict__ w1,
                                               const float* __restrict__ w2,
                                               const float* __restrict__ wk,
                                               const float* __restrict__ wv,
                                               const float* __restrict__ eg,
                                               const float* __restrict__ eb) {
    __shared__ float tile[32][33];
    int bid = blockIdx.x;
    if (bid < 128) {
        int i = bid * 256 + threadIdx.x;   // 0 .. 128*256-1
        int kp = i >> 8, c = i & 255;
        const float* srcs[4] = {w1, w2, wk, wv};
#pragma unroll
        for (int m = 0; m < 4; m++) {
            const float* w = srcs[m];
            g_wp[m][i] = packbf(w[(2 * kp) * 256 + c], w[(2 * kp + 1) * 256 + c]);
        }
    } else {
        int pid = bid - 128;                       // 0..2047
        int tok0 = (pid & 127) * 32;
        int d0 = ((pid >> 7) & 7) * 32;
        int z = pid >> 10;
        const float* src = z ? eb : eg;
        float* dst = z ? g_ebT : g_egT;
        int tx = threadIdx.x & 31, ty = threadIdx.x >> 5;  // 32 x 8
#pragma unroll
        for (int i = 0; i < 4; i++)
            tile[ty + 8 * i][tx] = src[(tok0 + ty + 8 * i) * 256 + d0 + tx];
        __syncthreads();
#pragma unroll
        for (int i = 0; i < 4; i++)
            dst[(d0 + ty + 8 * i) * 4096 + tok0 + tx] = tile[tx][ty + 8 * i];
    }
}

// ---------------- bf16 mma ----------------
__device__ __forceinline__ void mma16bf(float* c, const uint32_t a[4], uint32_t b0,
                                        uint32_t b1) {
    asm volatile(
        "mma.sync.aligned.m16n8k16.row.col.f32.bf16.bf16.f32 "
        "{%0,%1,%2,%3}, {%4,%5,%6,%7}, {%8,%9}, {%0,%1,%2,%3};"
        : "+f"(c[0]), "+f"(c[1]), "+f"(c[2]), "+f"(c[3])
        : "r"(a[0]), "r"(a[1]), "r"(a[2]), "r"(a[3]), "r"(b0), "r"(b1));
}

#define A_ST 132        // A smem row stride (uint32 pairs)
#define W_ST 264        // W smem row stride (uint32)
#define A_U32 (128 * A_ST)
#define WBUF_U32 (128 * W_ST)   // FULL weight matrix resident (128 pair-rows)

// 128x256x256 bf16 GEMM: A (smem pairs) @ W (global pairs) -> acc. 16 warps, 32x64 tiles.
// Whole W matrix staged in two cp.async halves; only 3 syncs per GEMM.
__device__ __forceinline__ void run_gemm(const uint32_t* __restrict__ Wg,
                                         const uint32_t* As, uint32_t* Wbuf,
                                         float acc[2][8][4], int wm, int wn,
                                         int lane, int tid) {
#pragma unroll
    for (int mt = 0; mt < 2; mt++)
#pragma unroll
        for (int nt = 0; nt < 8; nt++)
#pragma unroll
            for (int e = 0; e < 4; e++) acc[mt][nt][e] = 0.f;

    int g = lane >> 2, t = lane & 3;
    uint32_t wb = (uint32_t)__cvta_generic_to_shared(Wbuf);

    // stage both halves (64 pair-rows each); half0 then half1 as separate groups
#pragma unroll
    for (int h = 0; h < 2; h++) {
#pragma unroll
        for (int q = 0; q < 8; q++) {
            int idx = q * 512 + tid;          // 0..4095 granules of this half
            int row = h * 64 + (idx >> 6);
            int c4 = (idx & 63) * 4;
            uint32_t dst = wb + (uint32_t)((row * W_ST + c4) * 4);
            const uint32_t* src = Wg + row * 256 + c4;
            asm volatile("cp.async.cg.shared.global [%0], [%1], 16;" ::"r"(dst), "l"(src));
        }
        asm volatile("cp.async.commit_group;");
    }

    asm volatile("cp.async.wait_group 1;");   // half0 ready, half1 in flight
    __syncthreads();
#pragma unroll 2
    for (int kc = 0; kc < 8; kc++) {
        int k0p = kc * 8;
        uint32_t a[2][4];
#pragma unroll
        for (int mt = 0; mt < 2; mt++) {
            int r = wm * 32 + mt * 16 + g;
            a[mt][0] = As[r * A_ST + k0p + t];
            a[mt][1] = As[(r + 8) * A_ST + k0p + t];
            a[mt][2] = As[r * A_ST + k0p + t + 4];
            a[mt][3] = As[(r + 8) * A_ST + k0p + t + 4];
        }
#pragma unroll
        for (int nt = 0; nt < 8; nt++) {
            int c = wn * 64 + nt * 8 + g;
            uint32_t b0 = Wbuf[(k0p + t) * W_ST + c];
            uint32_t b1 = Wbuf[(k0p + t + 4) * W_ST + c];
            mma16bf(acc[0][nt], a[0], b0, b1);
            mma16bf(acc[1][nt], a[1], b0, b1);
        }
    }
    asm volatile("cp.async.wait_group 0;");   // half1 ready
    __syncthreads();
#pragma unroll 2
    for (int kc = 8; kc < 16; kc++) {
        int k0p = kc * 8;
        uint32_t a[2][4];
#pragma unroll
        for (int mt = 0; mt < 2; mt++) {
            int r = wm * 32 + mt * 16 + g;
            a[mt][0] = As[r * A_ST + k0p + t];
            a[mt][1] = As[(r + 8) * A_ST + k0p + t];
            a[mt][2] = As[r * A_ST + k0p + t + 4];
            a[mt][3] = As[(r + 8) * A_ST + k0p + t + 4];
        }
#pragma unroll
        for (int nt = 0; nt < 8; nt++) {
            int c = wn * 64 + nt * 8 + g;
            uint32_t b0 = Wbuf[(k0p + t) * W_ST + c];
            uint32_t b1 = Wbuf[(k0p + t + 4) * W_ST + c];
            mma16bf(acc[0][nt], a[0], b0, b1);
            mma16bf(acc[1][nt], a[1], b0, b1);
        }
    }
    __syncthreads();   // all B reads done before Wbuf is restaged / A rewritten
}

// ---------------- K1: fused bf16 tensor-core encoder (512 threads) ----------------
__global__ void __launch_bounds__(512, 1) k_encoder(
    const float* __restrict__ x, const float* __restrict__ pos_w,
    const float* __restrict__ pos_b, const float* __restrict__ fm_b1,
    const float* __restrict__ fm_b2, const float* __restrict__ in_g,
    const float* __restrict__ in_b, const float* __restrict__ k_b,
    const float* __restrict__ v_b) {
    extern __shared__ char smraw[];
    uint32_t* A = (uint32_t*)smraw;               // 128*132 u32
    uint32_t* Wbuf = A + A_U32;                   // 128*264 u32 (full W)
    float* pw = (float*)(Wbuf + WBUF_U32);        // 1024
    float* pb = pw + 1024;                        // 256

    int b = blockIdx.y;
    int t0 = blockIdx.x * 128;
    int tid = threadIdx.x;
    int wid = tid >> 5, lane = tid & 31;
    int wm = wid & 3, wn = wid >> 2;              // 4 x 4 warp grid, tile 32x64
    int g = lane >> 2, t = lane & 3;

    for (int i = tid; i < 1024; i += 512) pw[i] = pos_w[i];
    if (tid < 256) pb[tid] = pos_b[tid];
    float mean = g_stats[b * 2 + 0], rstd = g_stats[b * 2 + 1];
    __syncthreads();

    // fused load: x + pos -> global LN -> enc_g/enc_b -> bf16 pack into A
    {
        int r2 = tid >> 2, qq = tid & 3;
        int tok = t0 + r2;
        int ti = tok >> 6, tj = tok & 63;
        float fi = ti * (1.0f / 63.0f), fj = tj * (1.0f / 63.0f);
#pragma unroll 4
        for (int i = 0; i < 32; i++) {
            int p = qq * 32 + i;
            int d0 = 2 * p, d1 = d0 + 1;
            float p0 = fi * pw[d0] + fj * pw[256 + d0] + (1.0f - fi) * pw[512 + d0] +
                       (1.0f - fj) * pw[768 + d0] + pb[d0];
            float p1 = fi * pw[d1] + fj * pw[256 + d1] + (1.0f - fi) * pw[512 + d1] +
                       (1.0f - fj) * pw[768 + d1] + pb[d1];
            float x0 = x[(b * 256 + d0) * 4096 + tok];
            float x1 = x[(b * 256 + d1) * 4096 + tok];
            float e0 = g_egT[d0 * 4096 + tok], e1 = g_egT[d1 * 4096 + tok];
            float c0 = g_ebT[d0 * 4096 + tok], c1 = g_ebT[d1 * 4096 + tok];
            float v0 = (x0 + p0 - mean) * rstd * e0 + c0;
            float v1 = (x1 + p1 - mean) * rstd * e1 + c1;
            A[r2 * A_ST + p] = packbf(v0, v1);
        }
    }
    __syncthreads();

    float acc[2][8][4];

    // GEMM1 + relu -> A
    run_gemm(g_wp[0], A, Wbuf, acc, wm, wn, lane, tid);
#pragma unroll
    for (int nt = 0; nt < 8; nt++) {
        int c = wn * 64 + nt * 8 + 2 * t;
        int p = c >> 1;
        float2 bb = *(const float2*)&fm_b1[c];
#pragma unroll
        for (int mt = 0; mt < 2; mt++) {
            int r = wm * 32 + mt * 16 + g;
            float* a = acc[mt][nt];
            A[r * A_ST + p] = packbf(fmaxf(a[0] + bb.x, 0.f), fmaxf(a[1] + bb.y, 0.f));
            A[(r + 8) * A_ST + p] =
                packbf(fmaxf(a[2] + bb.x, 0.f), fmaxf(a[3] + bb.y, 0.f));
        }
    }
    __syncthreads();

    // GEMM2 + relu -> A
    run_gemm(g_wp[1], A, Wbuf, acc, wm, wn, lane, tid);
#pragma unroll
    for (int nt = 0; nt < 8; nt++) {
        int c = wn * 64 + nt * 8 + 2 * t;
        int p = c >> 1;
        float2 bb = *(const float2*)&fm_b2[c];
#pragma unroll
        for (int mt = 0; mt < 2; mt++) {
            int r = wm * 32 + mt * 16 + g;
            float* a = acc[mt][nt];
            A[r * A_ST + p] = packbf(fmaxf(a[0] + bb.x, 0.f), fmaxf(a[1] + bb.y, 0.f));
            A[(r + 8) * A_ST + p] =
                packbf(fmaxf(a[2] + bb.x, 0.f), fmaxf(a[3] + bb.y, 0.f));
        }
    }
    __syncthreads();

    // per-token LayerNorm over D (16 warps x 8 rows)
    for (int rr = 0; rr < 8; rr++) {
        int r = wid * 8 + rr;
        float2 vv[4];
        float s1 = 0.f, s2 = 0.f;
#pragma unroll
        for (int u = 0; u < 4; u++) {
            vv[u] = unpackbf(A[r * A_ST + lane + 32 * u]);
            s1 += vv[u].x + vv[u].y;
            s2 += vv[u].x * vv[u].x + vv[u].y * vv[u].y;
        }
        s1 = warp_sum(s1);
        s2 = warp_sum(s2);
        float mu = s1 * (1.0f / 256.0f);
        float rsd = rsqrtf(s2 * (1.0f / 256.0f) - mu * mu + 1e-5f);
#pragma unroll
        for (int u = 0; u < 4; u++) {
            int p = lane + 32 * u;
            float2 ig = *(const float2*)&in_g[2 * p];
            float2 ib = *(const float2*)&in_b[2 * p];
            A[r * A_ST + p] = packbf((vv[u].x - mu) * rsd * ig.x + ib.x,
                                     (vv[u].y - mu) * rsd * ig.y + ib.y);
        }
    }
    __syncthreads();

    // k projection -> g_kb (bf16 pairs)
    run_gemm(g_wp[2], A, Wbuf, acc, wm, wn, lane, tid);
#pragma unroll
    for (int nt = 0; nt < 8; nt++) {
        int c = wn * 64 + nt * 8 + 2 * t;
        int p = c >> 1;
        float2 bb = *(const float2*)&k_b[c];
#pragma unroll
        for (int mt = 0; mt < 2; mt++) {
            int r = wm * 32 + mt * 16 + g;
            float* a = acc[mt][nt];
            g_kb[((size_t)(b * 4096 + t0 + r)) * 128 + p] =
                packbf(a[0] + bb.x, a[1] + bb.y);
            g_kb[((size_t)(b * 4096 + t0 + r + 8)) * 128 + p] =
                packbf(a[2] + bb.x, a[3] + bb.y);
        }
    }

    // v projection -> g_vb (bf16 pairs)
    run_gemm(g_wp[3], A, Wbuf, acc, wm, wn, lane, tid);
#pragma unroll
    for (int nt = 0; nt < 8; nt++) {
        int c = wn * 64 + nt * 8 + 2 * t;
        int p = c >> 1;
        float2 bb = *(const float2*)&v_b[c];
#pragma unroll
        for (int mt = 0; mt < 2; mt++) {
            int r = wm * 32 + mt * 16 + g;
            float* a = acc[mt][nt];
            g_vb[((size_t)(b * 4096 + t0 + r)) * 128 + p] =
                packbf(a[0] + bb.x, a[1] + bb.y);
            g_vb[((size_t)(b * 4096 + t0 + r + 8)) * 128 + p] =
                packbf(a[2] + bb.x, a[3] + bb.y);
        }
    }
}

// ---------------- slot init ----------------
__global__ void k_init(const float* __restrict__ eps, const float* __restrict__ loc,
                       const float* __restrict__ lsc) {
    int b = blockIdx.x, tid = threadIdx.x;
    for (int idx = tid; idx < 2048; idx += 256) {
        int d = idx & 255;
        g_slots[b * 2048 + idx] = loc[d] + __expf(lsc[d]) * eps[b * 2048 + idx];
    }
}

// ---------------- per-iter: slot LN + q projection (scaled, fp32) ----------------
__global__ void __launch_bounds__(256) k_q(const float* __restrict__ q_w,
                                           const float* __restrict__ q_b,
                                           const float* __restrict__ slot_g,
                                           const float* __restrict__ slot_b) {
    __shared__ float ss[8 * 256];
    int b = blockIdx.x, tid = threadIdx.x, w = tid >> 5, lane = tid & 31;
    {
        float vv[8];
        float s1 = 0.f, s2 = 0.f;
#pragma unroll
        for (int u = 0; u < 8; u++) {
            vv[u] = g_slots[(b * 8 + w) * 256 + lane + 32 * u];
            s1 += vv[u];
            s2 += vv[u] * vv[u];
        }
        s1 = warp_sum(s1);
        s2 = warp_sum(s2);
        float mu = s1 * (1.0f / 256.0f);
        float rsd = rsqrtf(s2 * (1.0f / 256.0f) - mu * mu + 1e-5f);
#pragma unroll
        for (int u = 0; u < 8; u++) {
            int d = lane + 32 * u;
            ss[w * 256 + d] = (vv[u] - mu) * rsd * slot_g[d] + slot_b[d];
        }
    }
    __syncthreads();
    float acc[8];
#pragma unroll
    for (int i = 0; i < 8; i++) acc[i] = 0.f;
    for (int k = 0; k < 256; k++) {
        float wv = q_w[k * 256 + tid];
#pragma unroll
        for (int i = 0; i < 8; i++) acc[i] += ss[i * 256 + k] * wv;
    }
    float qb = q_b[tid];
#pragma unroll
    for (int i = 0; i < 8; i++)
        g_q[(b * 8 + i) * 256 + tid] = (acc[i] + qb) * 0.0625f;  // * D^-0.5
}

// ---------------- per-iter: streaming attention (bf16 k/v, pipelined) ----------------
#define CH 16
#define KVSTu 136                       // u32 per row, halves at 0 / 68
#define STG_U32 (2 * CH * KVSTu)        // 4352: k then v
#define QST 264                         // floats, halves at 0 / 132
#define ATTN_SMEM_BYTES (3 * STG_U32 * 4 + (8 * QST + CH * 9) * 4)

__global__ void __launch_bounds__(256) k_attn() {
    extern __shared__ char smraw[];
    uint32_t* stg = (uint32_t*)smraw;
    float* qs = (float*)(stg + 3 * STG_U32);
    float* dt = qs + 8 * QST;
    int tile = blockIdx.x, b = blockIdx.y;
    int tid = threadIdx.x;
    uint32_t smbase = (uint32_t)__cvta_generic_to_shared(stg);

    // stage q with h-split (float f -> +4 if f>=128)
    for (int i = tid; i < 2048; i += 256) {
        int s = i >> 8, f = i & 255;
        qs[s * QST + f + ((f >= 128) ? 4 : 0)] = g_q[b * 2048 + i];
    }

    int tb0 = tile * 128;

    auto stage = [&](int c) {
        unsigned st = ((unsigned)c) % 3u;
        uint32_t sb = smbase + st * STG_U32 * 4;
#pragma unroll
        for (int e = 0; e < 2; e++) {
            int gidx = tid * 2 + e;                 // 0..511
            int row = gidx >> 5, g32 = gidx & 31;   // 32 granules/row
            uint32_t off = (uint32_t)((g32 * 4 + ((g32 >= 16) ? 4 : 0)) * 4);
            size_t gsrc = ((size_t)(b * 4096 + tb0 + c * CH + row)) * 128 + g32 * 4;
            uint32_t kdst = sb + (uint32_t)(row * KVSTu * 4) + off;
            asm volatile("cp.async.cg.shared.global [%0], [%1], 16;" ::"r"(kdst),
                         "l"(g_kb + gsrc));
            asm volatile("cp.async.cg.shared.global [%0], [%1], 16;" ::"r"(
                             kdst + CH * KVSTu * 4),
                         "l"(g_vb + gsrc));
        }
        asm volatile("cp.async.commit_group;");
    };
    stage(0);
    stage(1);

    int t_d = tid >> 4, s_d = (tid >> 1) & 7, h_d = tid & 1;
    int s_v = tid >> 5, dc = tid & 31;
    uint32_t voff = dc * 4 + ((dc >= 16) ? 4 : 0);
    float av[8];
#pragma unroll
    for (int i2 = 0; i2 < 8; i2++) av[i2] = 0.f;
    float psreg = 0.f;

    for (int c = 0; c < 8; c++) {
        asm volatile("cp.async.wait_group 1;");
        __syncthreads();
        if (c + 2 < 8) stage(c + 2);
        else asm volatile("cp.async.commit_group;");
        const uint32_t* kb = stg + (((unsigned)c) % 3u) * STG_U32;
        const uint32_t* vb = kb + CH * KVSTu;
        // dots: thread = (token, slot, half)
        {
            const uint32_t* krow = kb + t_d * KVSTu + h_d * 68;
            const float* qrow = qs + s_d * QST + h_d * 132;
            float p = 0.f;
#pragma unroll
            for (int i = 0; i < 16; i++) {
                uint4 kq = *(const uint4*)(krow + i * 4);
                float4 q0 = *(const float4*)(qrow + i * 8);
                float4 q1 = *(const float4*)(qrow + i * 8 + 4);
                float2 f0 = unpackbf(kq.x), f1 = unpackbf(kq.y);
                float2 f2 = unpackbf(kq.z), f3 = unpackbf(kq.w);
                p += f0.x * q0.x + f0.y * q0.y + f1.x * q0.z + f1.y * q0.w;
                p += f2.x * q1.x + f2.y * q1.y + f3.x * q1.z + f3.y * q1.w;
            }
            p += __shfl_xor_sync(0xffffffffu, p, 1);
            if (h_d == 0) dt[t_d * 9 + s_d] = p;
        }
        __syncthreads();
        // softmax over slots, per token
        if (tid < CH) {
            float e[8], m = -1e30f;
#pragma unroll
            for (int s = 0; s < 8; s++) {
                e[s] = dt[tid * 9 + s];
                m = fmaxf(m, e[s]);
            }
            float tot = 0.f;
#pragma unroll
            for (int s = 0; s < 8; s++) {
                e[s] = __expf(e[s] - m);
                tot += e[s];
            }
            float inv = 1.f / tot;
#pragma unroll
            for (int s = 0; s < 8; s++) dt[tid * 9 + s] = e[s] * inv + 1e-8f;
        }
        __syncthreads();
        if (tid < 8) {
#pragma unroll
            for (int t = 0; t < CH; t++) psreg += dt[t * 9 + tid];
        }
        // v accumulate: thread = (slot, d-chunk of 8)
#pragma unroll 4
        for (int t = 0; t < CH; t++) {
            float a = dt[t * 9 + s_v];
            uint4 vq = *(const uint4*)(vb + t * KVSTu + voff);
            float2 f0 = unpackbf(vq.x), f1 = unpackbf(vq.y);
            float2 f2 = unpackbf(vq.z), f3 = unpackbf(vq.w);
            av[0] += a * f0.x; av[1] += a * f0.y;
            av[2] += a * f1.x; av[3] += a * f1.y;
            av[4] += a * f2.x; av[5] += a * f2.y;
            av[6] += a * f3.x; av[7] += a * f3.y;
        }
    }
    size_t obase = ((size_t)(b * 32 + tile)) * 2048 + s_v * 256 + dc * 8;
    *(float4*)&g_upd_part[obase] = make_float4(av[0], av[1], av[2], av[3]);
    *(float4*)&g_upd_part[obase + 4] = make_float4(av[4], av[5], av[6], av[7]);
    if (tid < 8) g_psum_part[(b * 32 + tile) * 8 + tid] = psreg;
}

// ---------------- per-iter: finalize upd (deterministic fixed-order reduce) ----------------
__global__ void __launch_bounds__(256) k_upd() {
    int b = blockIdx.x, tid = threadIdx.x;
    __shared__ float ps[8];
    if (tid < 8) {
        float s = 0.f;
        for (int tl = 0; tl < 32; tl++) s += g_psum_part[(b * 32 + tl) * 8 + tid];
        ps[tid] = s;
    }
    __syncthreads();
#pragma unroll
    for (int i = 0; i < 8; i++) {
        float s = 0.f;
        for (int tl = 0; tl < 32; tl++)
            s += g_upd_part[((size_t)(b * 32 + tl)) * 2048 + i * 256 + tid];
        g_upd[b * 2048 + i * 256 + tid] = s / ps[i];
    }
}

// ---------------- per-iter: GRU gate GEMMs (3 blocks per batch) ----------------
__global__ void __launch_bounds__(256) k_gates(const float* __restrict__ wih,
                                               const float* __restrict__ whh,
                                               const float* __restrict__ bih,
                                               const float* __restrict__ bhh) {
    __shared__ float u[2048], pv[2048];
    int b = blockIdx.x, cc = blockIdx.y, tid = threadIdx.x;
    for (int i = tid; i < 2048; i += 256) {
        u[i] = g_upd[b * 2048 + i];
        pv[i] = g_slots[b * 2048 + i];
    }
    __syncthreads();
    int c = cc * 256 + tid;
    float aI[8], aH[8];
    float bi = bih[c], bh = bhh[c];
#pragma unroll
    for (int s = 0; s < 8; s++) { aI[s] = bi; aH[s] = bh; }
    for (int k = 0; k < 256; k++) {
        float wi = wih[k * 768 + c], wh = whh[k * 768 + c];
#pragma unroll
        for (int s = 0; s < 8; s++) {
            aI[s] += u[s * 256 + k] * wi;
            aH[s] += pv[s * 256 + k] * wh;
        }
    }
#pragma unroll
    for (int s = 0; s < 8; s++) {
        g_gi[(b * 8 + s) * 768 + c] = aI[s];
        g_gh[(b * 8 + s) * 768 + c] = aH[s];
    }
}

// ---------------- per-iter: GRU pointwise + residual slot MLP (+ final output) --------
__global__ void __launch_bounds__(256) k_gru2(
    const float* __restrict__ pre_g, const float* __restrict__ pre_b,
    const float* __restrict__ w1, const float* __restrict__ b1,
    const float* __restrict__ w2, const float* __restrict__ b2,
    float* __restrict__ out, int wout) {
    __shared__ float hn[2048], ff[2048], mid[2048];
    int b = blockIdx.x, tid = threadIdx.x;
#pragma unroll
    for (int s = 0; s < 8; s++) {
        size_t gb = (size_t)(b * 8 + s) * 768 + tid;
        float r = 1.f / (1.f + __expf(-(g_gi[gb] + g_gh[gb])));
        float z = 1.f / (1.f + __expf(-(g_gi[gb + 256] + g_gh[gb + 256])));
        float n = tanhf(g_gi[gb + 512] + r * g_gh[gb + 512]);
        hn[s * 256 + tid] = (1.f - z) * n + z * g_slots[b * 2048 + s * 256 + tid];
    }
    __syncthreads();
    {
        int w = tid >> 5, lane = tid & 31;
        float vv[8];
        float s1 = 0.f, s2 = 0.f;
#pragma unroll
        for (int uu = 0; uu < 8; uu++) {
            vv[uu] = hn[w * 256 + lane + 32 * uu];
            s1 += vv[uu];
            s2 += vv[uu] * vv[uu];
        }
        s1 = warp_sum(s1);
        s2 = warp_sum(s2);
        float mu = s1 * (1.0f / 256.0f);
        float rsd = rsqrtf(s2 * (1.0f / 256.0f) - mu * mu + 1e-5f);
#pragma unroll
        for (int uu = 0; uu < 8; uu++) {
            int d = lane + 32 * uu;
            ff[w * 256 + d] = (vv[uu] - mu) * rsd * pre_g[d] + pre_b[d];
        }
    }
    __syncthreads();
    {
        float acc[8];
        float bb = b1[tid];
#pragma unroll
        for (int s = 0; s < 8; s++) acc[s] = bb;
        for (int k = 0; k < 256; k++) {
            float wv = w1[k * 256 + tid];
#pragma unroll
            for (int s = 0; s < 8; s++) acc[s] += ff[s * 256 + k] * wv;
        }
#pragma unroll
        for (int s = 0; s < 8; s++) mid[s * 256 + tid] = fmaxf(acc[s], 0.f);
    }
    __syncthreads();
    {
        float acc[8];
        float bb = b2[tid];
#pragma unroll
        for (int s = 0; s < 8; s++) acc[s] = bb;
        for (int k = 0; k < 256; k++) {
            float wv = w2[k * 256 + tid];
#pragma unroll
            for (int s = 0; s < 8; s++) acc[s] += mid[s * 256 + k] * wv;
        }
#pragma unroll
        for (int s = 0; s < 8; s++) {
            float res = hn[s * 256 + tid] + fmaxf(acc[s], 0.f);
            g_slots[b * 2048 + s * 256 + tid] = res;
            if (wout) out[b * 2048 + s * 256 + tid] = res;
        }
    }
}

// ---------------- host launcher ----------------
extern "C" void kernel_launch(void* const* d_in, const int* in_sizes, int n_in,
                              void* d_out, int out_size) {
    const float* x          = (const float*)d_in[0];
    const float* eps_noise  = (const float*)d_in[1];
    const float* pos_w      = (const float*)d_in[2];
    const float* pos_b      = (const float*)d_in[3];
    const float* enc_g      = (const float*)d_in[4];
    const float* enc_b      = (const float*)d_in[5];
    const float* fm_w1      = (const float*)d_in[6];
    const float* fm_b1      = (const float*)d_in[7];
    const float* fm_w2      = (const float*)d_in[8];
    const float* fm_b2      = (const float*)d_in[9];
    const float* in_g       = (const float*)d_in[10];
    const float* in_b       = (const float*)d_in[11];
    const float* q_w        = (const float*)d_in[12];
    const float* q_b        = (const float*)d_in[13];
    const float* k_w        = (const float*)d_in[14];
    const float* k_b        = (const float*)d_in[15];
    const float* v_w        = (const float*)d_in[16];
    const float* v_b        = (const float*)d_in[17];
    const float* gru_wih    = (const float*)d_in[18];
    const float* gru_whh    = (const float*)d_in[19];
    const float* gru_bih    = (const float*)d_in[20];
    const float* gru_bhh    = (const float*)d_in[21];
    const float* pre_g      = (const float*)d_in[22];
    const float* pre_b      = (const float*)d_in[23];
    const float* st_w1      = (const float*)d_in[24];
    const float* st_b1      = (const float*)d_in[25];
    const float* st_w2      = (const float*)d_in[26];
    const float* st_b2      = (const float*)d_in[27];
    const float* slot_g     = (const float*)d_in[28];
    const float* slot_b     = (const float*)d_in[29];
    const float* slots_loc  = (const float*)d_in[30];
    const float* slots_lsc  = (const float*)d_in[31];

    const int ENC_SMEM = (A_U32 + WBUF_U32) * 4 + (1024 + 256) * 4;  // 207872
    const int ATTN_SMEM = ATTN_SMEM_BYTES;                           // 61248

    cudaFuncSetAttribute(k_encoder, cudaFuncAttributeMaxDynamicSharedMemorySize, ENC_SMEM);
    cudaFuncSetAttribute(k_attn, cudaFuncAttributeMaxDynamicSharedMemorySize, ATTN_SMEM);

    // launch order chosen so k_encoder is the 4th launch (ncu captures launch #4)
    k_stats<<<dim3(32, 64), 256>>>(x, pos_w, pos_b);
    k_stats2<<<32, 64>>>();
    k_cvtW2<<<2176, 256>>>(fm_w1, fm_w2, k_w, v_w, enc_g, enc_b);
    k_encoder<<<dim3(32, 32), 512, ENC_SMEM>>>(x, pos_w, pos_b, fm_b1, fm_b2, in_g, in_b,
                                               k_b, v_b);
    k_init<<<32, 256>>>(eps_noise, slots_loc, slots_lsc);
    for (int it = 0; it < 3; it++) {
        k_q<<<32, 256>>>(q_w, q_b, slot_g, slot_b);
        k_attn<<<dim3(32, 32), 256, ATTN_SMEM>>>();
        k_upd<<<32, 256>>>();
        k_gates<<<dim3(32, 3), 256>>>(gru_wih, gru_whh, gru_bih, gru_bhh);
        k_gru2<<<32, 256>>>(pre_g, pre_b, st_w1, st_b1, st_w2, st_b2,
                            (float*)d_out, it == 2 ? 1 : 0);
    }
}

// round 10
// speedup vs baseline: 1.0171x; 1.0171x over previous
#include <cuda_runtime.h>
#include <cuda_bf16.h>
#include <math.h>
#include <stdint.h>

#define NB 32
#define ND 256
#define NTOK 4096
#define NSLOT 8

// ---------------- scratch (device globals; no allocation allowed) ----------------
__device__ uint32_t g_kb[NB * NTOK * 128];     // bf16-pair packed k: 67 MB
__device__ uint32_t g_vb[NB * NTOK * 128];     // bf16-pair packed v: 67 MB
__device__ uint32_t g_wp[4][ND * 128];         // n-major bf16-pair weights: [n][kpair]
__device__ float g_egT[ND * NTOK];             // transposed enc_g [d][tok]
__device__ float g_ebT[ND * NTOK];             // transposed enc_b [d][tok]
__device__ float g_stats_part[NB * 64 * 2];
__device__ float g_stats[NB * 2];              // mean, rstd per batch
__device__ float g_slots[NB * NSLOT * ND];
__device__ float g_q[NB * NSLOT * ND];
__device__ float g_upd_part[NB * 32 * NSLOT * ND];
__device__ float g_psum_part[NB * 32 * NSLOT];
__device__ float g_upd[NB * NSLOT * ND];
__device__ float g_gi[NB * NSLOT * 768];
__device__ float g_gh[NB * NSLOT * 768];

__device__ __forceinline__ float warp_sum(float v) {
#pragma unroll
    for (int o = 16; o; o >>= 1) v += __shfl_xor_sync(0xffffffffu, v, o);
    return v;
}

__device__ __forceinline__ uint32_t packbf(float a, float b) {
    __nv_bfloat162 h = __floats2bfloat162_rn(a, b);  // .x = a (low), .y = b (high)
    return *(uint32_t*)&h;
}
__device__ __forceinline__ float2 unpackbf(uint32_t u) {
    __nv_bfloat162 h = *(__nv_bfloat162*)&u;
    return __bfloat1622float2(h);
}

// ---------------- K0: per-batch sum / sumsq of h = x + pos (exact fp32) ----------------
__global__ void __launch_bounds__(256) k_stats(const float* __restrict__ x,
                                               const float* __restrict__ pos_w,
                                               const float* __restrict__ pos_b) {
    int b = blockIdx.x, c = blockIdx.y, tid = threadIdx.x;
    float s = 0.f, q = 0.f;
    int base = c * 16384;
    for (int e = base + tid; e < base + 16384; e += 256) {
        int d = e >> 12;
        int ij = e & 4095;
        int ti = ij >> 6, tj = ij & 63;
        float fi = ti * (1.0f / 63.0f), fj = tj * (1.0f / 63.0f);
        float p = fi * pos_w[d] + fj * pos_w[256 + d] + (1.0f - fi) * pos_w[512 + d] +
                  (1.0f - fj) * pos_w[768 + d] + pos_b[d];
        float v = x[b * 1048576 + e] + p;
        s += v;
        q += v * v;
    }
    s = warp_sum(s);
    q = warp_sum(q);
    __shared__ float rs[8], rq[8];
    int w = tid >> 5, lane = tid & 31;
    if (lane == 0) { rs[w] = s; rq[w] = q; }
    __syncthreads();
    if (tid == 0) {
        float S = 0.f, Q = 0.f;
#pragma unroll
        for (int i = 0; i < 8; i++) { S += rs[i]; Q += rq[i]; }
        g_stats_part[(b * 64 + c) * 2 + 0] = S;
        g_stats_part[(b * 64 + c) * 2 + 1] = Q;
    }
}

// ---------------- K0b: finalize per-batch stats (parallel tree in double) ----------------
__global__ void __launch_bounds__(64) k_stats2() {
    __shared__ double rs[64], rq[64];
    int b = blockIdx.x, tid = threadIdx.x;
    rs[tid] = (double)g_stats_part[(b * 64 + tid) * 2 + 0];
    rq[tid] = (double)g_stats_part[(b * 64 + tid) * 2 + 1];
    __syncthreads();
#pragma unroll
    for (int o = 32; o; o >>= 1) {
        if (tid < o) {
            rs[tid] += rs[tid + o];
            rq[tid] += rq[tid + o];
        }
        __syncthreads();
    }
    if (tid == 0) {
        double N = 1048576.0;
        double mu = rs[0] / N;
        double var = rq[0] / N - mu * mu;
        g_stats[b * 2 + 0] = (float)mu;
        g_stats[b * 2 + 1] = (float)(1.0 / sqrt(var + 1e-5));
    }
}

// ------- weight pre-pack to n-major bf16 pairs + enc_g/enc_b transpose (merged) -------
__global__ void __launch_bounds__(256) k_cvtW2(const float* __restrict__ w1,
                                               const float* __restrict__ w2,
                                               const float* __restrict__ wk,
                                               const float* __restrict__ wv,
                                               const float* __restrict__ eg,
                                               const float* __restrict__ eb) {
    __shared__ uint32_t tile[32][33];
    int bid = blockIdx.x;
    int tx = threadIdx.x & 31, ty = threadIdx.x >> 5;  // 32 x 8
    if (bid < 128) {
        // weights: n-major pack with smem transpose.
        // bid -> m (4), kpt (4 tiles of 32 kpairs), nt (8 tiles of 32 n)
        int m = bid >> 5, rem = bid & 31;
        int kpt = rem >> 3, nt = rem & 7;
        const float* srcs[4] = {w1, w2, wk, wv};
        const float* w = srcs[m];
#pragma unroll
        for (int i = 0; i < 4; i++) {
            int kp = kpt * 32 + ty + 8 * i;
            int n = nt * 32 + tx;
            tile[ty + 8 * i][tx] = packbf(w[(2 * kp) * 256 + n], w[(2 * kp + 1) * 256 + n]);
        }
        __syncthreads();
#pragma unroll
        for (int i = 0; i < 4; i++) {
            int n = nt * 32 + ty + 8 * i;
            int kp = kpt * 32 + tx;
            g_wp[m][n * 128 + kp] = tile[tx][ty + 8 * i];
        }
    } else {
        int pid = bid - 128;                       // 0..2047
        int tok0 = (pid & 127) * 32;
        int d0 = ((pid >> 7) & 7) * 32;
        int z = pid >> 10;
        const float* src = z ? eb : eg;
        float* dst = z ? g_ebT : g_egT;
#pragma unroll
        for (int i = 0; i < 4; i++)
            tile[ty + 8 * i][tx] =
                __float_as_uint(src[(tok0 + ty + 8 * i) * 256 + d0 + tx]);
        __syncthreads();
#pragma unroll
        for (int i = 0; i < 4; i++)
            dst[(d0 + ty + 8 * i) * 4096 + tok0 + tx] =
                __uint_as_float(tile[tx][ty + 8 * i]);
    }
}

// ---------------- bf16 mma + ldmatrix ----------------
__device__ __forceinline__ void mma16bf(float* c, const uint32_t a[4], uint32_t b0,
                                        uint32_t b1) {
    asm volatile(
        "mma.sync.aligned.m16n8k16.row.col.f32.bf16.bf16.f32 "
        "{%0,%1,%2,%3}, {%4,%5,%6,%7}, {%8,%9}, {%0,%1,%2,%3};"
        : "+f"(c[0]), "+f"(c[1]), "+f"(c[2]), "+f"(c[3])
        : "r"(a[0]), "r"(a[1]), "r"(a[2]), "r"(a[3]), "r"(b0), "r"(b1));
}

__device__ __forceinline__ void ldsm4(uint32_t f[4], uint32_t addr) {
    asm volatile("ldmatrix.sync.aligned.m8n8.x4.shared.b16 {%0,%1,%2,%3}, [%4];"
                 : "=r"(f[0]), "=r"(f[1]), "=r"(f[2]), "=r"(f[3])
                 : "r"(addr));
}

#define A_ST 132        // A smem row stride (u32 pairs); 528B -> LDSM conflict-free
#define W_ST 132        // W smem row stride (u32 kpairs); 528B -> LDSM conflict-free
#define A_U32 (128 * A_ST)
#define WBUF_U32 (256 * W_ST)   // FULL n-major W resident (256 n-rows x 128 kpairs)

// 128x256x256 bf16 GEMM via ldmatrix fragments. 16 warps, 32x64 warp tiles.
// W staged whole in two k-halves; 3 syncs per GEMM.
__device__ __forceinline__ void run_gemm(const uint32_t* __restrict__ Wg,
                                         uint32_t a_sh, uint32_t w_sh,
                                         uint32_t rowA0, uint32_t rowA1,
                                         const uint32_t rowB[4],
                                         float acc[2][8][4], int tid) {
#pragma unroll
    for (int mt = 0; mt < 2; mt++)
#pragma unroll
        for (int nt = 0; nt < 8; nt++)
#pragma unroll
            for (int e = 0; e < 4; e++) acc[mt][nt][e] = 0.f;

    // stage both k-halves (cols 0..63 then 64..127 of every n-row)
#pragma unroll
    for (int h = 0; h < 2; h++) {
#pragma unroll
        for (int q = 0; q < 8; q++) {
            int idx = q * 512 + tid;          // 0..4095 granules of this half
            int n = idx >> 4;
            int col = h * 64 + (idx & 15) * 4;
            uint32_t dst = w_sh + (uint32_t)((n * W_ST + col) * 4);
            const uint32_t* src = Wg + n * 128 + col;
            asm volatile("cp.async.cg.shared.global [%0], [%1], 16;" ::"r"(dst), "l"(src));
        }
        asm volatile("cp.async.commit_group;");
    }

    asm volatile("cp.async.wait_group 1;");   // half0 ready
    __syncthreads();
#pragma unroll
    for (int kc = 0; kc < 8; kc++) {
        uint32_t k0p = kc * 8;
        uint32_t fa0[4], fa1[4];
        ldsm4(fa0, a_sh + (rowA0 + k0p) * 4);
        ldsm4(fa1, a_sh + (rowA1 + k0p) * 4);
#pragma unroll
        for (int ntp = 0; ntp < 4; ntp++) {
            uint32_t fb[4];
            ldsm4(fb, w_sh + (rowB[ntp] + k0p) * 4);
            mma16bf(acc[0][2 * ntp], fa0, fb[0], fb[1]);
            mma16bf(acc[1][2 * ntp], fa1, fb[0], fb[1]);
            mma16bf(acc[0][2 * ntp + 1], fa0, fb[2], fb[3]);
            mma16bf(acc[1][2 * ntp + 1], fa1, fb[2], fb[3]);
        }
    }
    asm volatile("cp.async.wait_group 0;");   // half1 ready
    __syncthreads();
#pragma unroll
    for (int kc = 8; kc < 16; kc++) {
        uint32_t k0p = kc * 8;
        uint32_t fa0[4], fa1[4];
        ldsm4(fa0, a_sh + (rowA0 + k0p) * 4);
        ldsm4(fa1, a_sh + (rowA1 + k0p) * 4);
#pragma unroll
        for (int ntp = 0; ntp < 4; ntp++) {
            uint32_t fb[4];
            ldsm4(fb, w_sh + (rowB[ntp] + k0p) * 4);
            mma16bf(acc[0][2 * ntp], fa0, fb[0], fb[1]);
            mma16bf(acc[1][2 * ntp], fa1, fb[0], fb[1]);
            mma16bf(acc[0][2 * ntp + 1], fa0, fb[2], fb[3]);
            mma16bf(acc[1][2 * ntp + 1], fa1, fb[2], fb[3]);
        }
    }
    __syncthreads();   // all W/A reads done before restage / A rewrite
}

// ---------------- K1: fused bf16 tensor-core encoder (512 threads) ----------------
__global__ void __launch_bounds__(512, 1) k_encoder(
    const float* __restrict__ x, const float* __restrict__ pos_w,
    const float* __restrict__ pos_b, const float* __restrict__ fm_b1,
    const float* __restrict__ fm_b2, const float* __restrict__ in_g,
    const float* __restrict__ in_b, const float* __restrict__ k_b,
    const float* __restrict__ v_b) {
    extern __shared__ char smraw[];
    uint32_t* A = (uint32_t*)smraw;               // 128*132 u32
    uint32_t* Wbuf = A + A_U32;                   // 256*132 u32 (full n-major W)
    float* pw = (float*)(Wbuf + WBUF_U32);        // 1024
    float* pb = pw + 1024;                        // 256

    int b = blockIdx.y;
    int t0 = blockIdx.x * 128;
    int tid = threadIdx.x;
    int wid = tid >> 5, lane = tid & 31;
    int wm = wid & 3, wn = wid >> 2;              // 4 x 4 warp grid, tile 32x64
    int g = lane >> 2, t = lane & 3;

    uint32_t a_sh = (uint32_t)__cvta_generic_to_shared(A);
    uint32_t w_sh = (uint32_t)__cvta_generic_to_shared(Wbuf);

    // ldmatrix lane-address offsets (u32 units, without the per-chunk k0p)
    int sub = lane >> 3, wi = lane & 7;
    uint32_t rowA0 = (uint32_t)((wm * 32 + 0 + (sub & 1) * 8 + wi) * A_ST + (sub >> 1) * 4);
    uint32_t rowA1 = (uint32_t)((wm * 32 + 16 + (sub & 1) * 8 + wi) * A_ST + (sub >> 1) * 4);
    uint32_t rowB[4];
#pragma unroll
    for (int ntp = 0; ntp < 4; ntp++)
        rowB[ntp] =
            (uint32_t)((wn * 64 + ntp * 16 + (sub >> 1) * 8 + wi) * W_ST + (sub & 1) * 4);

    for (int i = tid; i < 1024; i += 512) pw[i] = pos_w[i];
    if (tid < 256) pb[tid] = pos_b[tid];
    float mean = g_stats[b * 2 + 0], rstd = g_stats[b * 2 + 1];
    __syncthreads();

    // fused load: x + pos -> global LN -> enc_g/enc_b -> bf16 pack into A
    {
        int r2 = tid >> 2, qq = tid & 3;
        int tok = t0 + r2;
        int ti = tok >> 6, tj = tok & 63;
        float fi = ti * (1.0f / 63.0f), fj = tj * (1.0f / 63.0f);
#pragma unroll 4
        for (int i = 0; i < 32; i++) {
            int p = qq * 32 + i;
            int d0 = 2 * p, d1 = d0 + 1;
            float p0 = fi * pw[d0] + fj * pw[256 + d0] + (1.0f - fi) * pw[512 + d0] +
                       (1.0f - fj) * pw[768 + d0] + pb[d0];
            float p1 = fi * pw[d1] + fj * pw[256 + d1] + (1.0f - fi) * pw[512 + d1] +
                       (1.0f - fj) * pw[768 + d1] + pb[d1];
            float x0 = x[(b * 256 + d0) * 4096 + tok];
            float x1 = x[(b * 256 + d1) * 4096 + tok];
            float e0 = g_egT[d0 * 4096 + tok], e1 = g_egT[d1 * 4096 + tok];
            float c0 = g_ebT[d0 * 4096 + tok], c1 = g_ebT[d1 * 4096 + tok];
            float v0 = (x0 + p0 - mean) * rstd * e0 + c0;
            float v1 = (x1 + p1 - mean) * rstd * e1 + c1;
            A[r2 * A_ST + p] = packbf(v0, v1);
        }
    }
    __syncthreads();

    float acc[2][8][4];

    // GEMM1 + relu -> A
    run_gemm(g_wp[0], a_sh, w_sh, rowA0, rowA1, rowB, acc, tid);
#pragma unroll
    for (int nt = 0; nt < 8; nt++) {
        int c = wn * 64 + nt * 8 + 2 * t;
        int p = c >> 1;
        float2 bb = *(const float2*)&fm_b1[c];
#pragma unroll
        for (int mt = 0; mt < 2; mt++) {
            int r = wm * 32 + mt * 16 + g;
            float* a = acc[mt][nt];
            A[r * A_ST + p] = packbf(fmaxf(a[0] + bb.x, 0.f), fmaxf(a[1] + bb.y, 0.f));
            A[(r + 8) * A_ST + p] =
                packbf(fmaxf(a[2] + bb.x, 0.f), fmaxf(a[3] + bb.y, 0.f));
        }
    }
    __syncthreads();

    // GEMM2 + relu -> A
    run_gemm(g_wp[1], a_sh, w_sh, rowA0, rowA1, rowB, acc, tid);
#pragma unroll
    for (int nt = 0; nt < 8; nt++) {
        int c = wn * 64 + nt * 8 + 2 * t;
        int p = c >> 1;
        float2 bb = *(const float2*)&fm_b2[c];
#pragma unroll
        for (int mt = 0; mt < 2; mt++) {
            int r = wm * 32 + mt * 16 + g;
            float* a = acc[mt][nt];
            A[r * A_ST + p] = packbf(fmaxf(a[0] + bb.x, 0.f), fmaxf(a[1] + bb.y, 0.f));
            A[(r + 8) * A_ST + p] =
                packbf(fmaxf(a[2] + bb.x, 0.f), fmaxf(a[3] + bb.y, 0.f));
        }
    }
    __syncthreads();

    // per-token LayerNorm over D (16 warps x 8 rows)
    for (int rr = 0; rr < 8; rr++) {
        int r = wid * 8 + rr;
        float2 vv[4];
        float s1 = 0.f, s2 = 0.f;
#pragma unroll
        for (int u = 0; u < 4; u++) {
            vv[u] = unpackbf(A[r * A_ST + lane + 32 * u]);
            s1 += vv[u].x + vv[u].y;
            s2 += vv[u].x * vv[u].x + vv[u].y * vv[u].y;
        }
        s1 = warp_sum(s1);
        s2 = warp_sum(s2);
        float mu = s1 * (1.0f / 256.0f);
        float rsd = rsqrtf(s2 * (1.0f / 256.0f) - mu * mu + 1e-5f);
#pragma unroll
        for (int u = 0; u < 4; u++) {
            int p = lane + 32 * u;
            float2 ig = *(const float2*)&in_g[2 * p];
            float2 ib = *(const float2*)&in_b[2 * p];
            A[r * A_ST + p] = packbf((vv[u].x - mu) * rsd * ig.x + ib.x,
                                     (vv[u].y - mu) * rsd * ig.y + ib.y);
        }
    }
    __syncthreads();

    // k projection -> g_kb (bf16 pairs)
    run_gemm(g_wp[2], a_sh, w_sh, rowA0, rowA1, rowB, acc, tid);
#pragma unroll
    for (int nt = 0; nt < 8; nt++) {
        int c = wn * 64 + nt * 8 + 2 * t;
        int p = c >> 1;
        float2 bb = *(const float2*)&k_b[c];
#pragma unroll
        for (int mt = 0; mt < 2; mt++) {
            int r = wm * 32 + mt * 16 + g;
            float* a = acc[mt][nt];
            g_kb[((size_t)(b * 4096 + t0 + r)) * 128 + p] =
                packbf(a[0] + bb.x, a[1] + bb.y);
            g_kb[((size_t)(b * 4096 + t0 + r + 8)) * 128 + p] =
                packbf(a[2] + bb.x, a[3] + bb.y);
        }
    }

    // v projection -> g_vb (bf16 pairs)
    run_gemm(g_wp[3], a_sh, w_sh, rowA0, rowA1, rowB, acc, tid);
#pragma unroll
    for (int nt = 0; nt < 8; nt++) {
        int c = wn * 64 + nt * 8 + 2 * t;
        int p = c >> 1;
        float2 bb = *(const float2*)&v_b[c];
#pragma unroll
        for (int mt = 0; mt < 2; mt++) {
            int r = wm * 32 + mt * 16 + g;
            float* a = acc[mt][nt];
            g_vb[((size_t)(b * 4096 + t0 + r)) * 128 + p] =
                packbf(a[0] + bb.x, a[1] + bb.y);
            g_vb[((size_t)(b * 4096 + t0 + r + 8)) * 128 + p] =
                packbf(a[2] + bb.x, a[3] + bb.y);
        }
    }
}

// ---------------- slot init ----------------
__global__ void k_init(const float* __restrict__ eps, const float* __restrict__ loc,
                       const float* __restrict__ lsc) {
    int b = blockIdx.x, tid = threadIdx.x;
    for (int idx = tid; idx < 2048; idx += 256) {
        int d = idx & 255;
        g_slots[b * 2048 + idx] = loc[d] + __expf(lsc[d]) * eps[b * 2048 + idx];
    }
}

// ---------------- per-iter: slot LN + q projection (scaled, fp32) ----------------
__global__ void __launch_bounds__(256) k_q(const float* __restrict__ q_w,
                                           const float* __restrict__ q_b,
                                           const float* __restrict__ slot_g,
                                           const float* __restrict__ slot_b) {
    __shared__ float ss[8 * 256];
    int b = blockIdx.x, tid = threadIdx.x, w = tid >> 5, lane = tid & 31;
    {
        float vv[8];
        float s1 = 0.f, s2 = 0.f;
#pragma unroll
        for (int u = 0; u < 8; u++) {
            vv[u] = g_slots[(b * 8 + w) * 256 + lane + 32 * u];
            s1 += vv[u];
            s2 += vv[u] * vv[u];
        }
        s1 = warp_sum(s1);
        s2 = warp_sum(s2);
        float mu = s1 * (1.0f / 256.0f);
        float rsd = rsqrtf(s2 * (1.0f / 256.0f) - mu * mu + 1e-5f);
#pragma unroll
        for (int u = 0; u < 8; u++) {
            int d = lane + 32 * u;
            ss[w * 256 + d] = (vv[u] - mu) * rsd * slot_g[d] + slot_b[d];
        }
    }
    __syncthreads();
    float acc[8];
#pragma unroll
    for (int i = 0; i < 8; i++) acc[i] = 0.f;
    for (int k = 0; k < 256; k++) {
        float wv = q_w[k * 256 + tid];
#pragma unroll
        for (int i = 0; i < 8; i++) acc[i] += ss[i * 256 + k] * wv;
    }
    float qb = q_b[tid];
#pragma unroll
    for (int i = 0; i < 8; i++)
        g_q[(b * 8 + i) * 256 + tid] = (acc[i] + qb) * 0.0625f;  // * D^-0.5
}

// ---------------- per-iter: streaming attention (bf16 k/v, pipelined) ----------------
#define CH 16
#define KVSTu 136                       // u32 per row, halves at 0 / 68
#define STG_U32 (2 * CH * KVSTu)        // 4352: k then v
#define QST 264                         // floats, halves at 0 / 132
#define ATTN_SMEM_BYTES (3 * STG_U32 * 4 + (8 * QST + CH * 9) * 4)

__global__ void __launch_bounds__(256) k_attn() {
    extern __shared__ char smraw[];
    uint32_t* stg = (uint32_t*)smraw;
    float* qs = (float*)(stg + 3 * STG_U32);
    float* dt = qs + 8 * QST;
    int tile = blockIdx.x, b = blockIdx.y;
    int tid = threadIdx.x;
    uint32_t smbase = (uint32_t)__cvta_generic_to_shared(stg);

    // stage q with h-split (float f -> +4 if f>=128)
    for (int i = tid; i < 2048; i += 256) {
        int s = i >> 8, f = i & 255;
        qs[s * QST + f + ((f >= 128) ? 4 : 0)] = g_q[b * 2048 + i];
    }

    int tb0 = tile * 128;

    auto stage = [&](int c) {
        unsigned st = ((unsigned)c) % 3u;
        uint32_t sb = smbase + st * STG_U32 * 4;
#pragma unroll
        for (int e = 0; e < 2; e++) {
            int gidx = tid * 2 + e;                 // 0..511
            int row = gidx >> 5, g32 = gidx & 31;   // 32 granules/row
            uint32_t off = (uint32_t)((g32 * 4 + ((g32 >= 16) ? 4 : 0)) * 4);
            size_t gsrc = ((size_t)(b * 4096 + tb0 + c * CH + row)) * 128 + g32 * 4;
            uint32_t kdst = sb + (uint32_t)(row * KVSTu * 4) + off;
            asm volatile("cp.async.cg.shared.global [%0], [%1], 16;" ::"r"(kdst),
                         "l"(g_kb + gsrc));
            asm volatile("cp.async.cg.shared.global [%0], [%1], 16;" ::"r"(
                             kdst + CH * KVSTu * 4),
                         "l"(g_vb + gsrc));
        }
        asm volatile("cp.async.commit_group;");
    };
    stage(0);
    stage(1);

    int t_d = tid >> 4, s_d = (tid >> 1) & 7, h_d = tid & 1;
    int s_v = tid >> 5, dc = tid & 31;
    uint32_t voff = dc * 4 + ((dc >= 16) ? 4 : 0);
    float av[8];
#pragma unroll
    for (int i2 = 0; i2 < 8; i2++) av[i2] = 0.f;
    float psreg = 0.f;

    for (int c = 0; c < 8; c++) {
        asm volatile("cp.async.wait_group 1;");
        __syncthreads();
        if (c + 2 < 8) stage(c + 2);
        else asm volatile("cp.async.commit_group;");
        const uint32_t* kb = stg + (((unsigned)c) % 3u) * STG_U32;
        const uint32_t* vb = kb + CH * KVSTu;
        // dots: thread = (token, slot, half)
        {
            const uint32_t* krow = kb + t_d * KVSTu + h_d * 68;
            const float* qrow = qs + s_d * QST + h_d * 132;
            float p = 0.f;
#pragma unroll
            for (int i = 0; i < 16; i++) {
                uint4 kq = *(const uint4*)(krow + i * 4);
                float4 q0 = *(const float4*)(qrow + i * 8);
                float4 q1 = *(const float4*)(qrow + i * 8 + 4);
                float2 f0 = unpackbf(kq.x), f1 = unpackbf(kq.y);
                float2 f2 = unpackbf(kq.z), f3 = unpackbf(kq.w);
                p += f0.x * q0.x + f0.y * q0.y + f1.x * q0.z + f1.y * q0.w;
                p += f2.x * q1.x + f2.y * q1.y + f3.x * q1.z + f3.y * q1.w;
            }
            p += __shfl_xor_sync(0xffffffffu, p, 1);
            if (h_d == 0) dt[t_d * 9 + s_d] = p;
        }
        __syncthreads();
        // softmax over slots, per token
        if (tid < CH) {
            float e[8], m = -1e30f;
#pragma unroll
            for (int s = 0; s < 8; s++) {
                e[s] = dt[tid * 9 + s];
                m = fmaxf(m, e[s]);
            }
            float tot = 0.f;
#pragma unroll
            for (int s = 0; s < 8; s++) {
                e[s] = __expf(e[s] - m);
                tot += e[s];
            }
            float inv = 1.f / tot;
#pragma unroll
            for (int s = 0; s < 8; s++) dt[tid * 9 + s] = e[s] * inv + 1e-8f;
        }
        __syncthreads();
        if (tid < 8) {
#pragma unroll
            for (int t = 0; t < CH; t++) psreg += dt[t * 9 + tid];
        }
        // v accumulate: thread = (slot, d-chunk of 8)
#pragma unroll 4
        for (int t = 0; t < CH; t++) {
            float a = dt[t * 9 + s_v];
            uint4 vq = *(const uint4*)(vb + t * KVSTu + voff);
            float2 f0 = unpackbf(vq.x), f1 = unpackbf(vq.y);
            float2 f2 = unpackbf(vq.z), f3 = unpackbf(vq.w);
            av[0] += a * f0.x; av[1] += a * f0.y;
            av[2] += a * f1.x; av[3] += a * f1.y;
            av[4] += a * f2.x; av[5] += a * f2.y;
            av[6] += a * f3.x; av[7] += a * f3.y;
        }
    }
    size_t obase = ((size_t)(b * 32 + tile)) * 2048 + s_v * 256 + dc * 8;
    *(float4*)&g_upd_part[obase] = make_float4(av[0], av[1], av[2], av[3]);
    *(float4*)&g_upd_part[obase + 4] = make_float4(av[4], av[5], av[6], av[7]);
    if (tid < 8) g_psum_part[(b * 32 + tile) * 8 + tid] = psreg;
}

// ---------------- per-iter: finalize upd (deterministic fixed-order reduce) ----------------
__global__ void __launch_bounds__(256) k_upd() {
    int b = blockIdx.x, tid = threadIdx.x;
    __shared__ float ps[8];
    if (tid < 8) {
        float s = 0.f;
        for (int tl = 0; tl < 32; tl++) s += g_psum_part[(b * 32 + tl) * 8 + tid];
        ps[tid] = s;
    }
    __syncthreads();
#pragma unroll
    for (int i = 0; i < 8; i++) {
        float s = 0.f;
        for (int tl = 0; tl < 32; tl++)
            s += g_upd_part[((size_t)(b * 32 + tl)) * 2048 + i * 256 + tid];
        g_upd[b * 2048 + i * 256 + tid] = s / ps[i];
    }
}

// ---------------- per-iter: GRU gate GEMMs (3 blocks per batch) ----------------
__global__ void __launch_bounds__(256) k_gates(const float* __restrict__ wih,
                                               const float* __restrict__ whh,
                                               const float* __restrict__ bih,
                                               const float* __restrict__ bhh) {
    __shared__ float u[2048], pv[2048];
    int b = blockIdx.x, cc = blockIdx.y, tid = threadIdx.x;
    for (int i = tid; i < 2048; i += 256) {
        u[i] = g_upd[b * 2048 + i];
        pv[i] = g_slots[b * 2048 + i];
    }
    __syncthreads();
    int c = cc * 256 + tid;
    float aI[8], aH[8];
    float bi = bih[c], bh = bhh[c];
#pragma unroll
    for (int s = 0; s < 8; s++) { aI[s] = bi; aH[s] = bh; }
    for (int k = 0; k < 256; k++) {
        float wi = wih[k * 768 + c], wh = whh[k * 768 + c];
#pragma unroll
        for (int s = 0; s < 8; s++) {
            aI[s] += u[s * 256 + k] * wi;
            aH[s] += pv[s * 256 + k] * wh;
        }
    }
#pragma unroll
    for (int s = 0; s < 8; s++) {
        g_gi[(b * 8 + s) * 768 + c] = aI[s];
        g_gh[(b * 8 + s) * 768 + c] = aH[s];
    }
}

// ---------------- per-iter: GRU pointwise + residual slot MLP (+ final output) --------
__global__ void __launch_bounds__(256) k_gru2(
    const float* __restrict__ pre_g, const float* __restrict__ pre_b,
    const float* __restrict__ w1, const float* __restrict__ b1,
    const float* __restrict__ w2, const float* __restrict__ b2,
    float* __restrict__ out, int wout) {
    __shared__ float hn[2048], ff[2048], mid[2048];
    int b = blockIdx.x, tid = threadIdx.x;
#pragma unroll
    for (int s = 0; s < 8; s++) {
        size_t gb = (size_t)(b * 8 + s) * 768 + tid;
        float r = 1.f / (1.f + __expf(-(g_gi[gb] + g_gh[gb])));
        float z = 1.f / (1.f + __expf(-(g_gi[gb + 256] + g_gh[gb + 256])));
        float n = tanhf(g_gi[gb + 512] + r * g_gh[gb + 512]);
        hn[s * 256 + tid] = (1.f - z) * n + z * g_slots[b * 2048 + s * 256 + tid];
    }
    __syncthreads();
    {
        int w = tid >> 5, lane = tid & 31;
        float vv[8];
        float s1 = 0.f, s2 = 0.f;
#pragma unroll
        for (int uu = 0; uu < 8; uu++) {
            vv[uu] = hn[w * 256 + lane + 32 * uu];
            s1 += vv[uu];
            s2 += vv[uu] * vv[uu];
        }
        s1 = warp_sum(s1);
        s2 = warp_sum(s2);
        float mu = s1 * (1.0f / 256.0f);
        float rsd = rsqrtf(s2 * (1.0f / 256.0f) - mu * mu + 1e-5f);
#pragma unroll
        for (int uu = 0; uu < 8; uu++) {
            int d = lane + 32 * uu;
            ff[w * 256 + d] = (vv[uu] - mu) * rsd * pre_g[d] + pre_b[d];
        }
    }
    __syncthreads();
    {
        float acc[8];
        float bb = b1[tid];
#pragma unroll
        for (int s = 0; s < 8; s++) acc[s] = bb;
        for (int k = 0; k < 256; k++) {
            float wv = w1[k * 256 + tid];
#pragma unroll
            for (int s = 0; s < 8; s++) acc[s] += ff[s * 256 + k] * wv;
        }
#pragma unroll
        for (int s = 0; s < 8; s++) mid[s * 256 + tid] = fmaxf(acc[s], 0.f);
    }
    __syncthreads();
    {
        float acc[8];
        float bb = b2[tid];
#pragma unroll
        for (int s = 0; s < 8; s++) acc[s] = bb;
        for (int k = 0; k < 256; k++) {
            float wv = w2[k * 256 + tid];
#pragma unroll
            for (int s = 0; s < 8; s++) acc[s] += mid[s * 256 + k] * wv;
        }
#pragma unroll
        for (int s = 0; s < 8; s++) {
            float res = hn[s * 256 + tid] + fmaxf(acc[s], 0.f);
            g_slots[b * 2048 + s * 256 + tid] = res;
            if (wout) out[b * 2048 + s * 256 + tid] = res;
        }
    }
}

// ---------------- host launcher ----------------
extern "C" void kernel_launch(void* const* d_in, const int* in_sizes, int n_in,
                              void* d_out, int out_size) {
    const float* x          = (const float*)d_in[0];
    const float* eps_noise  = (const float*)d_in[1];
    const float* pos_w      = (const float*)d_in[2];
    const float* pos_b      = (const float*)d_in[3];
    const float* enc_g      = (const float*)d_in[4];
    const float* enc_b      = (const float*)d_in[5];
    const float* fm_w1      = (const float*)d_in[6];
    const float* fm_b1      = (const float*)d_in[7];
    const float* fm_w2      = (const float*)d_in[8];
    const float* fm_b2      = (const float*)d_in[9];
    const float* in_g       = (const float*)d_in[10];
    const float* in_b       = (const float*)d_in[11];
    const float* q_w        = (const float*)d_in[12];
    const float* q_b        = (const float*)d_in[13];
    const float* k_w        = (const float*)d_in[14];
    const float* k_b        = (const float*)d_in[15];
    const float* v_w        = (const float*)d_in[16];
    const float* v_b        = (const float*)d_in[17];
    const float* gru_wih    = (const float*)d_in[18];
    const float* gru_whh    = (const float*)d_in[19];
    const float* gru_bih    = (const float*)d_in[20];
    const float* gru_bhh    = (const float*)d_in[21];
    const float* pre_g      = (const float*)d_in[22];
    const float* pre_b      = (const float*)d_in[23];
    const float* st_w1      = (const float*)d_in[24];
    const float* st_b1      = (const float*)d_in[25];
    const float* st_w2      = (const float*)d_in[26];
    const float* st_b2      = (const float*)d_in[27];
    const float* slot_g     = (const float*)d_in[28];
    const float* slot_b     = (const float*)d_in[29];
    const float* slots_loc  = (const float*)d_in[30];
    const float* slots_lsc  = (const float*)d_in[31];

    const int ENC_SMEM = (A_U32 + WBUF_U32) * 4 + (1024 + 256) * 4;  // 207872
    const int ATTN_SMEM = ATTN_SMEM_BYTES;                           // 61248

    cudaFuncSetAttribute(k_encoder, cudaFuncAttributeMaxDynamicSharedMemorySize, ENC_SMEM);
    cudaFuncSetAttribute(k_attn, cudaFuncAttributeMaxDynamicSharedMemorySize, ATTN_SMEM);

    // launch order keeps k_encoder as the 4th launch (ncu captures launch #4)
    k_stats<<<dim3(32, 64), 256>>>(x, pos_w, pos_b);
    k_stats2<<<32, 64>>>();
    k_cvtW2<<<2176, 256>>>(fm_w1, fm_w2, k_w, v_w, enc_g, enc_b);
    k_encoder<<<dim3(32, 32), 512, ENC_SMEM>>>(x, pos_w, pos_b, fm_b1, fm_b2, in_g, in_b,
                                               k_b, v_b);
    k_init<<<32, 256>>>(eps_noise, slots_loc, slots_lsc);
    for (int it = 0; it < 3; it++) {
        k_q<<<32, 256>>>(q_w, q_b, slot_g, slot_b);
        k_attn<<<dim3(32, 32), 256, ATTN_SMEM>>>();
        k_upd<<<32, 256>>>();
        k_gates<<<dim3(32, 3), 256>>>(gru_wih, gru_whh, gru_bih, gru_bhh);
        k_gru2<<<32, 256>>>(pre_g, pre_b, st_w1, st_b1, st_w2, st_b2,
                            (float*)d_out, it == 2 ? 1 : 0);
    }
}

// round 12
// speedup vs baseline: 1.0679x; 1.0500x over previous
#include <cuda_runtime.h>
#include <cuda_bf16.h>
#include <math.h>
#include <stdint.h>

#define NB 32
#define ND 256
#define NTOK 4096
#define NSLOT 8

// ---------------- scratch (device globals; no allocation allowed) ----------------
__device__ uint32_t g_kb[NB * NTOK * 128];     // bf16-pair packed k: 67 MB
__device__ uint32_t g_vb[NB * NTOK * 128];     // bf16-pair packed v: 67 MB
__device__ uint32_t g_wp[4][ND * 128];         // n-major bf16-pair weights: [n][kpair]
__device__ float g_egT[ND * NTOK];             // transposed enc_g [d][tok]
__device__ float g_ebT[ND * NTOK];             // transposed enc_b [d][tok]
__device__ float g_stats_part[NB * 64 * 2];
__device__ float g_stats[NB * 2];              // mean, rstd per batch
__device__ float g_slots[NB * NSLOT * ND];
__device__ float g_q[NB * NSLOT * ND];
__device__ float g_upd_part[NB * 32 * NSLOT * ND];
__device__ float g_psum_part[NB * 32 * NSLOT];
__device__ float g_upd[NB * NSLOT * ND];
__device__ float g_gi[NB * NSLOT * 768];
__device__ float g_gh[NB * NSLOT * 768];

__device__ __forceinline__ float warp_sum(float v) {
#pragma unroll
    for (int o = 16; o; o >>= 1) v += __shfl_xor_sync(0xffffffffu, v, o);
    return v;
}

__device__ __forceinline__ uint32_t packbf(float a, float b) {
    __nv_bfloat162 h = __floats2bfloat162_rn(a, b);  // .x = a (low), .y = b (high)
    return *(uint32_t*)&h;
}
__device__ __forceinline__ float2 unpackbf(uint32_t u) {
    __nv_bfloat162 h = *(__nv_bfloat162*)&u;
    return __bfloat1622float2(h);
}

// ---------------- K0: per-batch sum / sumsq of h = x + pos (exact fp32) ----------------
__global__ void __launch_bounds__(256) k_stats(const float* __restrict__ x,
                                               const float* __restrict__ pos_w,
                                               const float* __restrict__ pos_b) {
    int b = blockIdx.x, c = blockIdx.y, tid = threadIdx.x;
    float s = 0.f, q = 0.f;
    int base = c * 16384;
    for (int e = base + tid; e < base + 16384; e += 256) {
        int d = e >> 12;
        int ij = e & 4095;
        int ti = ij >> 6, tj = ij & 63;
        float fi = ti * (1.0f / 63.0f), fj = tj * (1.0f / 63.0f);
        float p = fi * pos_w[d] + fj * pos_w[256 + d] + (1.0f - fi) * pos_w[512 + d] +
                  (1.0f - fj) * pos_w[768 + d] + pos_b[d];
        float v = x[b * 1048576 + e] + p;
        s += v;
        q += v * v;
    }
    s = warp_sum(s);
    q = warp_sum(q);
    __shared__ float rs[8], rq[8];
    int w = tid >> 5, lane = tid & 31;
    if (lane == 0) { rs[w] = s; rq[w] = q; }
    __syncthreads();
    if (tid == 0) {
        float S = 0.f, Q = 0.f;
#pragma unroll
        for (int i = 0; i < 8; i++) { S += rs[i]; Q += rq[i]; }
        g_stats_part[(b * 64 + c) * 2 + 0] = S;
        g_stats_part[(b * 64 + c) * 2 + 1] = Q;
    }
}

// ---------------- K0b: finalize per-batch stats (parallel tree in double) ----------------
__global__ void __launch_bounds__(64) k_stats2() {
    __shared__ double rs[64], rq[64];
    int b = blockIdx.x, tid = threadIdx.x;
    rs[tid] = (double)g_stats_part[(b * 64 + tid) * 2 + 0];
    rq[tid] = (double)g_stats_part[(b * 64 + tid) * 2 + 1];
    __syncthreads();
#pragma unroll
    for (int o = 32; o; o >>= 1) {
        if (tid < o) {
            rs[tid] += rs[tid + o];
            rq[tid] += rq[tid + o];
        }
        __syncthreads();
    }
    if (tid == 0) {
        double N = 1048576.0;
        double mu = rs[0] / N;
        double var = rq[0] / N - mu * mu;
        g_stats[b * 2 + 0] = (float)mu;
        g_stats[b * 2 + 1] = (float)(1.0 / sqrt(var + 1e-5));
    }
}

// ------- weight pre-pack to n-major bf16 pairs + enc_g/enc_b transpose (merged) -------
__global__ void __launch_bounds__(256) k_cvtW2(const float* __restrict__ w1,
                                               const float* __restrict__ w2,
                                               const float* __restrict__ wk,
                                               const float* __restrict__ wv,
                                               const float* __restrict__ eg,
                                               const float* __restrict__ eb) {
    __shared__ uint32_t tile[32][33];
    int bid = blockIdx.x;
    int tx = threadIdx.x & 31, ty = threadIdx.x >> 5;  // 32 x 8
    if (bid < 128) {
        int m = bid >> 5, rem = bid & 31;
        int kpt = rem >> 3, nt = rem & 7;
        const float* srcs[4] = {w1, w2, wk, wv};
        const float* w = srcs[m];
#pragma unroll
        for (int i = 0; i < 4; i++) {
            int kp = kpt * 32 + ty + 8 * i;
            int n = nt * 32 + tx;
            tile[ty + 8 * i][tx] = packbf(w[(2 * kp) * 256 + n], w[(2 * kp + 1) * 256 + n]);
        }
        __syncthreads();
#pragma unroll
        for (int i = 0; i < 4; i++) {
            int n = nt * 32 + ty + 8 * i;
            int kp = kpt * 32 + tx;
            g_wp[m][n * 128 + kp] = tile[tx][ty + 8 * i];
        }
    } else {
        int pid = bid - 128;                       // 0..2047
        int tok0 = (pid & 127) * 32;
        int d0 = ((pid >> 7) & 7) * 32;
        int z = pid >> 10;
        const float* src = z ? eb : eg;
        float* dst = z ? g_ebT : g_egT;
#pragma unroll
        for (int i = 0; i < 4; i++)
            tile[ty + 8 * i][tx] =
                __float_as_uint(src[(tok0 + ty + 8 * i) * 256 + d0 + tx]);
        __syncthreads();
#pragma unroll
        for (int i = 0; i < 4; i++)
            dst[(d0 + ty + 8 * i) * 4096 + tok0 + tx] =
                __uint_as_float(tile[tx][ty + 8 * i]);
    }
}

// ---------------- shared helpers (both encoder variants) ----------------
__device__ __forceinline__ uint32_t swz16(uint32_t o) { return o ^ ((o >> 3) & 0x70); }

__device__ __forceinline__ void mma16bf(float* c, const uint32_t a[4], uint32_t b0,
                                        uint32_t b1) {
    asm volatile(
        "mma.sync.aligned.m16n8k16.row.col.f32.bf16.bf16.f32 "
        "{%0,%1,%2,%3}, {%4,%5,%6,%7}, {%8,%9}, {%0,%1,%2,%3};"
        : "+f"(c[0]), "+f"(c[1]), "+f"(c[2]), "+f"(c[3])
        : "r"(a[0]), "r"(a[1]), "r"(a[2]), "r"(a[3]), "r"(b0), "r"(b1));
}

__device__ __forceinline__ void ldsm4(uint32_t f[4], uint32_t addr) {
    asm volatile("ldmatrix.sync.aligned.m8n8.x4.shared.b16 {%0,%1,%2,%3}, [%4];"
                 : "=r"(f[0]), "=r"(f[1]), "=r"(f[2]), "=r"(f[3])
                 : "r"(addr));
}

#if !defined(__CUDA_ARCH__) || defined(__CUDA_ARCH_FEAT_SM103_ALL)
// ---------------- tcgen05 helpers (sm_103a-only compilation pass) ----------------
static constexpr uint64_t DESC_BASE_SW128 =
    (2ull << 61) | (1ull << 46) | (64ull << 32) | (1ull << 16);

__device__ __forceinline__ uint64_t mk_desc(uint32_t addr) {
    return DESC_BASE_SW128 | ((uint64_t)(addr >> 4) & 0x3FFF);
}

// idesc kind::f16: F32 acc, a=BF16, b=BF16, N=128, M=128
#define ENC_IDESC ((1u << 4) | (1u << 7) | (1u << 10) | (16u << 17) | (8u << 24))

__device__ __forceinline__ bool elect1() {
    uint32_t p;
    asm volatile(
        "{\n\t.reg .pred p;\n\telect.sync _|p, 0xFFFFFFFF;\n\tselp.b32 %0, 1, 0, p;\n\t}"
        : "=r"(p));
    return p != 0;
}

__device__ __forceinline__ void mma_f16_ss(uint32_t d_tmem, uint64_t a_desc,
                                           uint64_t b_desc, uint32_t idesc, bool accum) {
    uint32_t en = accum ? 1u : 0u;
    asm volatile(
        "{\n\t"
        ".reg .pred p;\n\t"
        "setp.ne.u32 p, %5, 0;\n\t"
        "tcgen05.mma.cta_group::1.kind::f16 [%0], %1, %2, %3, {%4, %4, %4, %4}, p;\n\t"
        "}"
        :: "r"(d_tmem), "l"(a_desc), "l"(b_desc), "r"(idesc), "r"(0u), "r"(en)
        : "memory");
}

__device__ __forceinline__ void mbar_wait(uint32_t mbar, uint32_t par) {
    uint32_t done;
    asm volatile(
        "{\n\t.reg .pred p;\n\t"
        "mbarrier.try_wait.parity.acquire.cta.shared::cta.b64 p, [%1], %2;\n\t"
        "selp.b32 %0, 1, 0, p;\n\t}"
        : "=r"(done) : "r"(mbar), "r"(par) : "memory");
    while (!done) {
        asm volatile(
            "{\n\t.reg .pred p;\n\t"
            "mbarrier.try_wait.parity.acquire.cta.shared::cta.b64 p, [%1], %2, 0x989680;\n\t"
            "selp.b32 %0, 1, 0, p;\n\t}"
            : "=r"(done) : "r"(mbar), "r"(par) : "memory");
    }
}

__device__ __forceinline__ void tmem_ld32(uint32_t* r, uint32_t taddr) {
    asm volatile(
        "tcgen05.ld.sync.aligned.32x32b.x32.b32 "
        "{%0, %1, %2, %3, %4, %5, %6, %7, "
        " %8, %9, %10, %11, %12, %13, %14, %15, "
        " %16, %17, %18, %19, %20, %21, %22, %23, "
        " %24, %25, %26, %27, %28, %29, %30, %31}, [%32];"
        : "=r"(r[0]),  "=r"(r[1]),  "=r"(r[2]),  "=r"(r[3]),
          "=r"(r[4]),  "=r"(r[5]),  "=r"(r[6]),  "=r"(r[7]),
          "=r"(r[8]),  "=r"(r[9]),  "=r"(r[10]), "=r"(r[11]),
          "=r"(r[12]), "=r"(r[13]), "=r"(r[14]), "=r"(r[15]),
          "=r"(r[16]), "=r"(r[17]), "=r"(r[18]), "=r"(r[19]),
          "=r"(r[20]), "=r"(r[21]), "=r"(r[22]), "=r"(r[23]),
          "=r"(r[24]), "=r"(r[25]), "=r"(r[26]), "=r"(r[27]),
          "=r"(r[28]), "=r"(r[29]), "=r"(r[30]), "=r"(r[31])
        : "r"(taddr));
}
#endif  // tcgen05 helpers

// tcgen05 smem layout (bytes, relative to 1024-aligned base)
#define ENC_PW 1024
#define ENC_PB 5120
#define ENC_A 6144                      // 128 rows x 256 bf16, SW128 blocked (64 KB)
#define ENC_B 71680                     // 256 rows x 256 bf16, SW128 blocked (128 KB)
// fallback (ldmatrix) layout constants
#define FB_A_ST 132
#define FB_W_ST 132
#define FB_A_U32 (128 * FB_A_ST)
#define FB_WBUF_U32 (256 * FB_W_ST)
#define ENC_SMEM_MAX 207872             // max(tcgen05 203776, fallback 207872)

#if defined(__CUDA_ARCH__) && !defined(__CUDA_ARCH_FEAT_SM103_ALL)
// fallback GEMM (R10 ldmatrix path) — compiled only for the portable-PTX pass
__device__ __forceinline__ void fb_run_gemm(const uint32_t* __restrict__ Wg,
                                            uint32_t a_sh, uint32_t w_sh,
                                            uint32_t rowA0, uint32_t rowA1,
                                            const uint32_t rowB[4],
                                            float acc[2][8][4], int tid) {
#pragma unroll
    for (int mt = 0; mt < 2; mt++)
#pragma unroll
        for (int nt = 0; nt < 8; nt++)
#pragma unroll
            for (int e = 0; e < 4; e++) acc[mt][nt][e] = 0.f;
#pragma unroll
    for (int h = 0; h < 2; h++) {
#pragma unroll
        for (int q = 0; q < 8; q++) {
            int idx = q * 512 + tid;
            int n = idx >> 4;
            int col = h * 64 + (idx & 15) * 4;
            uint32_t dst = w_sh + (uint32_t)((n * FB_W_ST + col) * 4);
            const uint32_t* src = Wg + n * 128 + col;
            asm volatile("cp.async.cg.shared.global [%0], [%1], 16;" ::"r"(dst), "l"(src));
        }
        asm volatile("cp.async.commit_group;");
    }
    asm volatile("cp.async.wait_group 1;");
    __syncthreads();
#pragma unroll
    for (int kc = 0; kc < 8; kc++) {
        uint32_t k0p = kc * 8;
        uint32_t fa0[4], fa1[4];
        ldsm4(fa0, a_sh + (rowA0 + k0p) * 4);
        ldsm4(fa1, a_sh + (rowA1 + k0p) * 4);
#pragma unroll
        for (int ntp = 0; ntp < 4; ntp++) {
            uint32_t fb[4];
            ldsm4(fb, w_sh + (rowB[ntp] + k0p) * 4);
            mma16bf(acc[0][2 * ntp], fa0, fb[0], fb[1]);
            mma16bf(acc[1][2 * ntp], fa1, fb[0], fb[1]);
            mma16bf(acc[0][2 * ntp + 1], fa0, fb[2], fb[3]);
            mma16bf(acc[1][2 * ntp + 1], fa1, fb[2], fb[3]);
        }
    }
    asm volatile("cp.async.wait_group 0;");
    __syncthreads();
#pragma unroll
    for (int kc = 8; kc < 16; kc++) {
        uint32_t k0p = kc * 8;
        uint32_t fa0[4], fa1[4];
        ldsm4(fa0, a_sh + (rowA0 + k0p) * 4);
        ldsm4(fa1, a_sh + (rowA1 + k0p) * 4);
#pragma unroll
        for (int ntp = 0; ntp < 4; ntp++) {
            uint32_t fb[4];
            ldsm4(fb, w_sh + (rowB[ntp] + k0p) * 4);
            mma16bf(acc[0][2 * ntp], fa0, fb[0], fb[1]);
            mma16bf(acc[1][2 * ntp], fa1, fb[0], fb[1]);
            mma16bf(acc[0][2 * ntp + 1], fa0, fb[2], fb[3]);
            mma16bf(acc[1][2 * ntp + 1], fa1, fb[2], fb[3]);
        }
    }
    __syncthreads();
}
#endif

// ---------------- K1: fused bf16 encoder (512 threads; tcgen05 on sm_103a) ----------------
__global__ void __launch_bounds__(512, 1) __cluster_dims__(1, 1, 1) k_encoder(
    const float* __restrict__ x, const float* __restrict__ pos_w,
    const float* __restrict__ pos_b, const float* __restrict__ fm_b1,
    const float* __restrict__ fm_b2, const float* __restrict__ in_g,
    const float* __restrict__ in_b, const float* __restrict__ k_b,
    const float* __restrict__ v_b) {
#if !defined(__CUDA_ARCH__) || defined(__CUDA_ARCH_FEAT_SM103_ALL)
    // ================== tcgen05 path ==================
    extern __shared__ char smraw[];
    uint32_t smb_raw = (uint32_t)__cvta_generic_to_shared(smraw);
    uint32_t smb = (smb_raw + 1023u) & ~1023u;
    char* smc = smraw + (smb - smb_raw);
    float* pw = (float*)(smc + ENC_PW);
    float* pb = (float*)(smc + ENC_PB);

    int b = blockIdx.y, t0 = blockIdx.x * 128;
    int tid = threadIdx.x, wid = tid >> 5, lane = tid & 31;

    if (tid == 0)
        asm volatile("mbarrier.init.shared.b64 [%0], %1;" ::"r"(smb + 8), "r"(1u)
                     : "memory");
    if (wid == 0)
        asm volatile(
            "tcgen05.alloc.cta_group::1.sync.aligned.shared::cta.b32 [%0], %1;" ::"r"(smb),
            "r"(256u)
            : "memory");

    auto stageB = [&](const uint32_t* __restrict__ Wg) {
#pragma unroll
        for (int q = 0; q < 16; q++) {
            int idx = q * 512 + tid;              // 0..8191 16B granules
            int n = idx >> 5, gg = idx & 31;
            uint32_t dst = smb + ENC_B + (uint32_t)(gg >> 3) * 32768u +
                           swz16((uint32_t)(n * 128 + (gg & 7) * 16));
            const uint32_t* src = Wg + n * 128 + gg * 4;
            asm volatile("cp.async.cg.shared.global [%0], [%1], 16;" ::"r"(dst), "l"(src));
        }
        asm volatile("cp.async.commit_group;" ::: "memory");
    };
    stageB(g_wp[0]);

    for (int i = tid; i < 1024; i += 512) pw[i] = pos_w[i];
    if (tid < 256) pb[tid] = pos_b[tid];
    __syncthreads();

    uint32_t tmem_base;
    asm volatile("ld.shared.b32 %0, [%1];" : "=r"(tmem_base) : "r"(smb));
    float mean = g_stats[b * 2 + 0], rstd = g_stats[b * 2 + 1];

    // fused load: x + pos -> global LN -> enc_g/enc_b -> bf16 pack into swizzled A
    {
        int r2 = tid >> 2, qq = tid & 3;
        int tok = t0 + r2;
        int ti = tok >> 6, tj = tok & 63;
        float fi = ti * (1.0f / 63.0f), fj = tj * (1.0f / 63.0f);
#pragma unroll 4
        for (int i = 0; i < 32; i++) {
            int p = qq * 32 + i;
            int d0 = 2 * p, d1 = d0 + 1;
            float p0 = fi * pw[d0] + fj * pw[256 + d0] + (1.0f - fi) * pw[512 + d0] +
                       (1.0f - fj) * pw[768 + d0] + pb[d0];
            float p1 = fi * pw[d1] + fj * pw[256 + d1] + (1.0f - fi) * pw[512 + d1] +
                       (1.0f - fj) * pw[768 + d1] + pb[d1];
            float x0 = x[(b * 256 + d0) * 4096 + tok];
            float x1 = x[(b * 256 + d1) * 4096 + tok];
            float e0 = g_egT[d0 * 4096 + tok], e1 = g_egT[d1 * 4096 + tok];
            float c0 = g_ebT[d0 * 4096 + tok], c1 = g_ebT[d1 * 4096 + tok];
            float v0 = (x0 + p0 - mean) * rstd * e0 + c0;
            float v1 = (x1 + p1 - mean) * rstd * e1 + c1;
            *(uint32_t*)(smc + ENC_A + qq * 16384 + swz16((uint32_t)(r2 * 128 + i * 4))) =
                packbf(v0, v1);
        }
    }

    int sub = wid & 3, cg = wid >> 2;
    int m = sub * 32 + lane;

#pragma unroll 1
    for (int g = 0; g < 4; g++) {
        asm volatile("fence.proxy.async.shared::cta;" ::: "memory");
        asm volatile("cp.async.wait_group 0;" ::: "memory");
        __syncthreads();
        if (wid == 0 && elect1()) {
            uint64_t a0 = mk_desc(smb + ENC_A);
            uint64_t b0 = mk_desc(smb + ENC_B);
#pragma unroll
            for (int nh = 0; nh < 2; nh++) {
#pragma unroll
                for (int s = 0; s < 16; s++) {
                    uint64_t ad = a0 + (uint64_t)((s >> 2) * 1024 + (s & 3) * 2);
                    uint64_t bd =
                        b0 + (uint64_t)(nh * 1024 + (s >> 2) * 2048 + (s & 3) * 2);
                    mma_f16_ss(tmem_base + nh * 128, ad, bd, ENC_IDESC, s > 0);
                }
            }
            asm volatile(
                "tcgen05.commit.cta_group::1.mbarrier::arrive::one.shared::cluster.b64 "
                "[%0];" ::"r"(smb + 8)
                : "memory");
        }
        mbar_wait(smb + 8, (uint32_t)(g & 1));
        asm volatile("tcgen05.fence::after_thread_sync;" ::: "memory");

        if (g == 0) stageB(g_wp[1]);
        else if (g == 1) stageB(g_wp[2]);
        else if (g == 2) stageB(g_wp[3]);

        uint32_t dr[64];
        tmem_ld32(dr, tmem_base + cg * 64);
        tmem_ld32(dr + 32, tmem_base + cg * 64 + 32);
        asm volatile("tcgen05.wait::ld.sync.aligned;" ::: "memory");

        if (g < 2) {
            const float* bias = (g == 0) ? fm_b1 : fm_b2;
#pragma unroll
            for (int j = 0; j < 32; j++) {
                float2 bb = *(const float2*)&bias[64 * cg + 2 * j];
                float v0 = fmaxf(__uint_as_float(dr[2 * j]) + bb.x, 0.f);
                float v1 = fmaxf(__uint_as_float(dr[2 * j + 1]) + bb.y, 0.f);
                *(uint32_t*)(smc + ENC_A + cg * 16384 +
                             swz16((uint32_t)(m * 128 + j * 4))) = packbf(v0, v1);
            }
            if (g == 1) {
                __syncthreads();
                for (int rr = 0; rr < 8; rr++) {
                    int r = wid * 8 + rr;
                    float2 vv[4];
                    float s1 = 0.f, s2 = 0.f;
#pragma unroll
                    for (int u = 0; u < 4; u++) {
                        uint32_t val = *(uint32_t*)(smc + ENC_A + u * 16384 +
                                                    swz16((uint32_t)(r * 128 + lane * 4)));
                        vv[u] = unpackbf(val);
                        s1 += vv[u].x + vv[u].y;
                        s2 += vv[u].x * vv[u].x + vv[u].y * vv[u].y;
                    }
                    s1 = warp_sum(s1);
                    s2 = warp_sum(s2);
                    float mu = s1 * (1.0f / 256.0f);
                    float rsd = rsqrtf(s2 * (1.0f / 256.0f) - mu * mu + 1e-5f);
#pragma unroll
                    for (int u = 0; u < 4; u++) {
                        int p = lane + 32 * u;
                        float2 ig = *(const float2*)&in_g[2 * p];
                        float2 ib = *(const float2*)&in_b[2 * p];
                        *(uint32_t*)(smc + ENC_A + u * 16384 +
                                     swz16((uint32_t)(r * 128 + lane * 4))) =
                            packbf((vv[u].x - mu) * rsd * ig.x + ib.x,
                                   (vv[u].y - mu) * rsd * ig.y + ib.y);
                    }
                }
            }
        } else {
            const float* bias = (g == 2) ? k_b : v_b;
            uint32_t* gout = (g == 2) ? g_kb : g_vb;
            uint32_t* dst = gout + ((size_t)(b * 4096 + t0 + m)) * 128 + cg * 32;
#pragma unroll
            for (int j = 0; j < 16; j++) {
                float2 bb0 = *(const float2*)&bias[64 * cg + 4 * j];
                float2 bb1 = *(const float2*)&bias[64 * cg + 4 * j + 2];
                uint2 vv;
                vv.x = packbf(__uint_as_float(dr[4 * j]) + bb0.x,
                              __uint_as_float(dr[4 * j + 1]) + bb0.y);
                vv.y = packbf(__uint_as_float(dr[4 * j + 2]) + bb1.x,
                              __uint_as_float(dr[4 * j + 3]) + bb1.y);
                *(uint2*)(dst + 2 * j) = vv;
            }
        }
    }
    __syncthreads();
    if (tid == 0)
        asm volatile("mbarrier.inval.shared.b64 [%0];" ::"r"(smb + 8) : "memory");
    if (wid == 0)
        asm volatile("tcgen05.dealloc.cta_group::1.sync.aligned.b32 %0, %1;" ::"r"(
                         tmem_base),
                     "r"(256u));
#else
    // ================== fallback ldmatrix path (portable PTX pass) ==================
    extern __shared__ char smraw[];
    uint32_t* A = (uint32_t*)smraw;
    uint32_t* Wbuf = A + FB_A_U32;
    float* pw = (float*)(Wbuf + FB_WBUF_U32);
    float* pb = pw + 1024;

    int b = blockIdx.y, t0 = blockIdx.x * 128;
    int tid = threadIdx.x, wid = tid >> 5, lane = tid & 31;
    int wm = wid & 3, wn = wid >> 2;
    int g = lane >> 2, t = lane & 3;

    uint32_t a_sh = (uint32_t)__cvta_generic_to_shared(A);
    uint32_t w_sh = (uint32_t)__cvta_generic_to_shared(Wbuf);

    int sub = lane >> 3, wi = lane & 7;
    uint32_t rowA0 =
        (uint32_t)((wm * 32 + 0 + (sub & 1) * 8 + wi) * FB_A_ST + (sub >> 1) * 4);
    uint32_t rowA1 =
        (uint32_t)((wm * 32 + 16 + (sub & 1) * 8 + wi) * FB_A_ST + (sub >> 1) * 4);
    uint32_t rowB[4];
#pragma unroll
    for (int ntp = 0; ntp < 4; ntp++)
        rowB[ntp] = (uint32_t)((wn * 64 + ntp * 16 + (sub >> 1) * 8 + wi) * FB_W_ST +
                               (sub & 1) * 4);

    for (int i = tid; i < 1024; i += 512) pw[i] = pos_w[i];
    if (tid < 256) pb[tid] = pos_b[tid];
    float mean = g_stats[b * 2 + 0], rstd = g_stats[b * 2 + 1];
    __syncthreads();

    {
        int r2 = tid >> 2, qq = tid & 3;
        int tok = t0 + r2;
        int ti = tok >> 6, tj = tok & 63;
        float fi = ti * (1.0f / 63.0f), fj = tj * (1.0f / 63.0f);
#pragma unroll 4
        for (int i = 0; i < 32; i++) {
            int p = qq * 32 + i;
            int d0 = 2 * p, d1 = d0 + 1;
            float p0 = fi * pw[d0] + fj * pw[256 + d0] + (1.0f - fi) * pw[512 + d0] +
                       (1.0f - fj) * pw[768 + d0] + pb[d0];
            float p1 = fi * pw[d1] + fj * pw[256 + d1] + (1.0f - fi) * pw[512 + d1] +
                       (1.0f - fj) * pw[768 + d1] + pb[d1];
            float x0 = x[(b * 256 + d0) * 4096 + tok];
            float x1 = x[(b * 256 + d1) * 4096 + tok];
            float e0 = g_egT[d0 * 4096 + tok], e1 = g_egT[d1 * 4096 + tok];
            float c0 = g_ebT[d0 * 4096 + tok], c1 = g_ebT[d1 * 4096 + tok];
            A[r2 * FB_A_ST + p] =
                packbf((x0 + p0 - mean) * rstd * e0 + c0, (x1 + p1 - mean) * rstd * e1 + c1);
        }
    }
    __syncthreads();

    float acc[2][8][4];

    fb_run_gemm(g_wp[0], a_sh, w_sh, rowA0, rowA1, rowB, acc, tid);
#pragma unroll
    for (int nt = 0; nt < 8; nt++) {
        int c = wn * 64 + nt * 8 + 2 * t;
        int p = c >> 1;
        float2 bb = *(const float2*)&fm_b1[c];
#pragma unroll
        for (int mt = 0; mt < 2; mt++) {
            int r = wm * 32 + mt * 16 + g;
            float* a = acc[mt][nt];
            A[r * FB_A_ST + p] = packbf(fmaxf(a[0] + bb.x, 0.f), fmaxf(a[1] + bb.y, 0.f));
            A[(r + 8) * FB_A_ST + p] =
                packbf(fmaxf(a[2] + bb.x, 0.f), fmaxf(a[3] + bb.y, 0.f));
        }
    }
    __syncthreads();

    fb_run_gemm(g_wp[1], a_sh, w_sh, rowA0, rowA1, rowB, acc, tid);
#pragma unroll
    for (int nt = 0; nt < 8; nt++) {
        int c = wn * 64 + nt * 8 + 2 * t;
        int p = c >> 1;
        float2 bb = *(const float2*)&fm_b2[c];
#pragma unroll
        for (int mt = 0; mt < 2; mt++) {
            int r = wm * 32 + mt * 16 + g;
            float* a = acc[mt][nt];
            A[r * FB_A_ST + p] = packbf(fmaxf(a[0] + bb.x, 0.f), fmaxf(a[1] + bb.y, 0.f));
            A[(r + 8) * FB_A_ST + p] =
                packbf(fmaxf(a[2] + bb.x, 0.f), fmaxf(a[3] + bb.y, 0.f));
        }
    }
    __syncthreads();

    for (int rr = 0; rr < 8; rr++) {
        int r = wid * 8 + rr;
        float2 vv[4];
        float s1 = 0.f, s2 = 0.f;
#pragma unroll
        for (int u = 0; u < 4; u++) {
            vv[u] = unpackbf(A[r * FB_A_ST + lane + 32 * u]);
            s1 += vv[u].x + vv[u].y;
            s2 += vv[u].x * vv[u].x + vv[u].y * vv[u].y;
        }
        s1 = warp_sum(s1);
        s2 = warp_sum(s2);
        float mu = s1 * (1.0f / 256.0f);
        float rsd = rsqrtf(s2 * (1.0f / 256.0f) - mu * mu + 1e-5f);
#pragma unroll
        for (int u = 0; u < 4; u++) {
            int p = lane + 32 * u;
            float2 ig = *(const float2*)&in_g[2 * p];
            float2 ib = *(const float2*)&in_b[2 * p];
            A[r * FB_A_ST + p] = packbf((vv[u].x - mu) * rsd * ig.x + ib.x,
                                        (vv[u].y - mu) * rsd * ig.y + ib.y);
        }
    }
    __syncthreads();

    fb_run_gemm(g_wp[2], a_sh, w_sh, rowA0, rowA1, rowB, acc, tid);
#pragma unroll
    for (int nt = 0; nt < 8; nt++) {
        int c = wn * 64 + nt * 8 + 2 * t;
        int p = c >> 1;
        float2 bb = *(const float2*)&k_b[c];
#pragma unroll
        for (int mt = 0; mt < 2; mt++) {
            int r = wm * 32 + mt * 16 + g;
            float* a = acc[mt][nt];
            g_kb[((size_t)(b * 4096 + t0 + r)) * 128 + p] = packbf(a[0] + bb.x, a[1] + bb.y);
            g_kb[((size_t)(b * 4096 + t0 + r + 8)) * 128 + p] =
                packbf(a[2] + bb.x, a[3] + bb.y);
        }
    }

    fb_run_gemm(g_wp[3], a_sh, w_sh, rowA0, rowA1, rowB, acc, tid);
#pragma unroll
    for (int nt = 0; nt < 8; nt++) {
        int c = wn * 64 + nt * 8 + 2 * t;
        int p = c >> 1;
        float2 bb = *(const float2*)&v_b[c];
#pragma unroll
        for (int mt = 0; mt < 2; mt++) {
            int r = wm * 32 + mt * 16 + g;
            float* a = acc[mt][nt];
            g_vb[((size_t)(b * 4096 + t0 + r)) * 128 + p] = packbf(a[0] + bb.x, a[1] + bb.y);
            g_vb[((size_t)(b * 4096 + t0 + r + 8)) * 128 + p] =
                packbf(a[2] + bb.x, a[3] + bb.y);
        }
    }
#endif
}

// ---------------- slot init ----------------
__global__ void k_init(const float* __restrict__ eps, const float* __restrict__ loc,
                       const float* __restrict__ lsc) {
    int b = blockIdx.x, tid = threadIdx.x;
    for (int idx = tid; idx < 2048; idx += 256) {
        int d = idx & 255;
        g_slots[b * 2048 + idx] = loc[d] + __expf(lsc[d]) * eps[b * 2048 + idx];
    }
}

// ---------------- per-iter: slot LN + q projection (scaled, fp32) ----------------
__global__ void __launch_bounds__(256) k_q(const float* __restrict__ q_w,
                                           const float* __restrict__ q_b,
                                           const float* __restrict__ slot_g,
                                           const float* __restrict__ slot_b) {
    __shared__ float ss[8 * 256];
    int b = blockIdx.x, tid = threadIdx.x, w = tid >> 5, lane = tid & 31;
    {
        float vv[8];
        float s1 = 0.f, s2 = 0.f;
#pragma unroll
        for (int u = 0; u < 8; u++) {
            vv[u] = g_slots[(b * 8 + w) * 256 + lane + 32 * u];
            s1 += vv[u];
            s2 += vv[u] * vv[u];
        }
        s1 = warp_sum(s1);
        s2 = warp_sum(s2);
        float mu = s1 * (1.0f / 256.0f);
        float rsd = rsqrtf(s2 * (1.0f / 256.0f) - mu * mu + 1e-5f);
#pragma unroll
        for (int u = 0; u < 8; u++) {
            int d = lane + 32 * u;
            ss[w * 256 + d] = (vv[u] - mu) * rsd * slot_g[d] + slot_b[d];
        }
    }
    __syncthreads();
    float acc[8];
#pragma unroll
    for (int i = 0; i < 8; i++) acc[i] = 0.f;
    for (int k = 0; k < 256; k++) {
        float wv = q_w[k * 256 + tid];
#pragma unroll
        for (int i = 0; i < 8; i++) acc[i] += ss[i * 256 + k] * wv;
    }
    float qb = q_b[tid];
#pragma unroll
    for (int i = 0; i < 8; i++)
        g_q[(b * 8 + i) * 256 + tid] = (acc[i] + qb) * 0.0625f;  // * D^-0.5
}

// ---------------- per-iter: streaming attention (bf16 k/v, pipelined) ----------------
#define CH 16
#define KVSTu 136                       // u32 per row, halves at 0 / 68
#define STG_U32 (2 * CH * KVSTu)        // 4352: k then v
#define QST 264                         // floats, halves at 0 / 132
#define ATTN_SMEM_BYTES (3 * STG_U32 * 4 + (8 * QST + CH * 9) * 4)

__global__ void __launch_bounds__(256) k_attn() {
    extern __shared__ char smraw[];
    uint32_t* stg = (uint32_t*)smraw;
    float* qs = (float*)(stg + 3 * STG_U32);
    float* dt = qs + 8 * QST;
    int tile = blockIdx.x, b = blockIdx.y;
    int tid = threadIdx.x;
    uint32_t smbase = (uint32_t)__cvta_generic_to_shared(stg);

    // stage q with h-split (float f -> +4 if f>=128)
    for (int i = tid; i < 2048; i += 256) {
        int s = i >> 8, f = i & 255;
        qs[s * QST + f + ((f >= 128) ? 4 : 0)] = g_q[b * 2048 + i];
    }

    int tb0 = tile * 128;

    auto stage = [&](int c) {
        unsigned st = ((unsigned)c) % 3u;
        uint32_t sb = smbase + st * STG_U32 * 4;
#pragma unroll
        for (int e = 0; e < 2; e++) {
            int gidx = tid * 2 + e;                 // 0..511
            int row = gidx >> 5, g32 = gidx & 31;   // 32 granules/row
            uint32_t off = (uint32_t)((g32 * 4 + ((g32 >= 16) ? 4 : 0)) * 4);
            size_t gsrc = ((size_t)(b * 4096 + tb0 + c * CH + row)) * 128 + g32 * 4;
            uint32_t kdst = sb + (uint32_t)(row * KVSTu * 4) + off;
            asm volatile("cp.async.cg.shared.global [%0], [%1], 16;" ::"r"(kdst),
                         "l"(g_kb + gsrc));
            asm volatile("cp.async.cg.shared.global [%0], [%1], 16;" ::"r"(
                             kdst + CH * KVSTu * 4),
                         "l"(g_vb + gsrc));
        }
        asm volatile("cp.async.commit_group;");
    };
    stage(0);
    stage(1);

    int t_d = tid >> 4, s_d = (tid >> 1) & 7, h_d = tid & 1;
    int s_v = tid >> 5, dc = tid & 31;
    uint32_t voff = dc * 4 + ((dc >= 16) ? 4 : 0);
    float av[8];
#pragma unroll
    for (int i2 = 0; i2 < 8; i2++) av[i2] = 0.f;
    float psreg = 0.f;

    for (int c = 0; c < 8; c++) {
        asm volatile("cp.async.wait_group 1;");
        __syncthreads();
        if (c + 2 < 8) stage(c + 2);
        else asm volatile("cp.async.commit_group;");
        const uint32_t* kb = stg + (((unsigned)c) % 3u) * STG_U32;
        const uint32_t* vb = kb + CH * KVSTu;
        {
            const uint32_t* krow = kb + t_d * KVSTu + h_d * 68;
            const float* qrow = qs + s_d * QST + h_d * 132;
            float p = 0.f;
#pragma unroll
            for (int i = 0; i < 16; i++) {
                uint4 kq = *(const uint4*)(krow + i * 4);
                float4 q0 = *(const float4*)(qrow + i * 8);
                float4 q1 = *(const float4*)(qrow + i * 8 + 4);
                float2 f0 = unpackbf(kq.x), f1 = unpackbf(kq.y);
                float2 f2 = unpackbf(kq.z), f3 = unpackbf(kq.w);
                p += f0.x * q0.x + f0.y * q0.y + f1.x * q0.z + f1.y * q0.w;
                p += f2.x * q1.x + f2.y * q1.y + f3.x * q1.z + f3.y * q1.w;
            }
            p += __shfl_xor_sync(0xffffffffu, p, 1);
            if (h_d == 0) dt[t_d * 9 + s_d] = p;
        }
        __syncthreads();
        if (tid < CH) {
            float e[8], m = -1e30f;
#pragma unroll
            for (int s = 0; s < 8; s++) {
                e[s] = dt[tid * 9 + s];
                m = fmaxf(m, e[s]);
            }
            float tot = 0.f;
#pragma unroll
            for (int s = 0; s < 8; s++) {
                e[s] = __expf(e[s] - m);
                tot += e[s];
            }
            float inv = 1.f / tot;
#pragma unroll
            for (int s = 0; s < 8; s++) dt[tid * 9 + s] = e[s] * inv + 1e-8f;
        }
        __syncthreads();
        if (tid < 8) {
#pragma unroll
            for (int t = 0; t < CH; t++) psreg += dt[t * 9 + tid];
        }
#pragma unroll 4
        for (int t = 0; t < CH; t++) {
            float a = dt[t * 9 + s_v];
            uint4 vq = *(const uint4*)(vb + t * KVSTu + voff);
            float2 f0 = unpackbf(vq.x), f1 = unpackbf(vq.y);
            float2 f2 = unpackbf(vq.z), f3 = unpackbf(vq.w);
            av[0] += a * f0.x; av[1] += a * f0.y;
            av[2] += a * f1.x; av[3] += a * f1.y;
            av[4] += a * f2.x; av[5] += a * f2.y;
            av[6] += a * f3.x; av[7] += a * f3.y;
        }
    }
    size_t obase = ((size_t)(b * 32 + tile)) * 2048 + s_v * 256 + dc * 8;
    *(float4*)&g_upd_part[obase] = make_float4(av[0], av[1], av[2], av[3]);
    *(float4*)&g_upd_part[obase + 4] = make_float4(av[4], av[5], av[6], av[7]);
    if (tid < 8) g_psum_part[(b * 32 + tile) * 8 + tid] = psreg;
}

// ---------------- per-iter: finalize upd (deterministic fixed-order reduce) ----------------
__global__ void __launch_bounds__(256) k_upd() {
    int b = blockIdx.x, tid = threadIdx.x;
    __shared__ float ps[8];
    if (tid < 8) {
        float s = 0.f;
        for (int tl = 0; tl < 32; tl++) s += g_psum_part[(b * 32 + tl) * 8 + tid];
        ps[tid] = s;
    }
    __syncthreads();
#pragma unroll
    for (int i = 0; i < 8; i++) {
        float s = 0.f;
        for (int tl = 0; tl < 32; tl++)
            s += g_upd_part[((size_t)(b * 32 + tl)) * 2048 + i * 256 + tid];
        g_upd[b * 2048 + i * 256 + tid] = s / ps[i];
    }
}

// ---------------- per-iter: GRU gate GEMMs (3 blocks per batch) ----------------
__global__ void __launch_bounds__(256) k_gates(const float* __restrict__ wih,
                                               const float* __restrict__ whh,
                                               const float* __restrict__ bih,
                                               const float* __restrict__ bhh) {
    __shared__ float u[2048], pv[2048];
    int b = blockIdx.x, cc = blockIdx.y, tid = threadIdx.x;
    for (int i = tid; i < 2048; i += 256) {
        u[i] = g_upd[b * 2048 + i];
        pv[i] = g_slots[b * 2048 + i];
    }
    __syncthreads();
    int c = cc * 256 + tid;
    float aI[8], aH[8];
    float bi = bih[c], bh = bhh[c];
#pragma unroll
    for (int s = 0; s < 8; s++) { aI[s] = bi; aH[s] = bh; }
    for (int k = 0; k < 256; k++) {
        float wi = wih[k * 768 + c], wh = whh[k * 768 + c];
#pragma unroll
        for (int s = 0; s < 8; s++) {
            aI[s] += u[s * 256 + k] * wi;
            aH[s] += pv[s * 256 + k] * wh;
        }
    }
#pragma unroll
    for (int s = 0; s < 8; s++) {
        g_gi[(b * 8 + s) * 768 + c] = aI[s];
        g_gh[(b * 8 + s) * 768 + c] = aH[s];
    }
}

// ---------------- per-iter: GRU pointwise + residual slot MLP (+ final output) --------
__global__ void __launch_bounds__(256) k_gru2(
    const float* __restrict__ pre_g, const float* __restrict__ pre_b,
    const float* __restrict__ w1, const float* __restrict__ b1,
    const float* __restrict__ w2, const float* __restrict__ b2,
    float* __restrict__ out, int wout) {
    __shared__ float hn[2048], ff[2048], mid[2048];
    int b = blockIdx.x, tid = threadIdx.x;
#pragma unroll
    for (int s = 0; s < 8; s++) {
        size_t gb = (size_t)(b * 8 + s) * 768 + tid;
        float r = 1.f / (1.f + __expf(-(g_gi[gb] + g_gh[gb])));
        float z = 1.f / (1.f + __expf(-(g_gi[gb + 256] + g_gh[gb + 256])));
        float n = tanhf(g_gi[gb + 512] + r * g_gh[gb + 512]);
        hn[s * 256 + tid] = (1.f - z) * n + z * g_slots[b * 2048 + s * 256 + tid];
    }
    __syncthreads();
    {
        int w = tid >> 5, lane = tid & 31;
        float vv[8];
        float s1 = 0.f, s2 = 0.f;
#pragma unroll
        for (int uu = 0; uu < 8; uu++) {
            vv[uu] = hn[w * 256 + lane + 32 * uu];
            s1 += vv[uu];
            s2 += vv[uu] * vv[uu];
        }
        s1 = warp_sum(s1);
        s2 = warp_sum(s2);
        float mu = s1 * (1.0f / 256.0f);
        float rsd = rsqrtf(s2 * (1.0f / 256.0f) - mu * mu + 1e-5f);
#pragma unroll
        for (int uu = 0; uu < 8; uu++) {
            int d = lane + 32 * uu;
            ff[w * 256 + d] = (vv[uu] - mu) * rsd * pre_g[d] + pre_b[d];
        }
    }
    __syncthreads();
    {
        float acc[8];
        float bb = b1[tid];
#pragma unroll
        for (int s = 0; s < 8; s++) acc[s] = bb;
        for (int k = 0; k < 256; k++) {
            float wv = w1[k * 256 + tid];
#pragma unroll
            for (int s = 0; s < 8; s++) acc[s] += ff[s * 256 + k] * wv;
        }
#pragma unroll
        for (int s = 0; s < 8; s++) mid[s * 256 + tid] = fmaxf(acc[s], 0.f);
    }
    __syncthreads();
    {
        float acc[8];
        float bb = b2[tid];
#pragma unroll
        for (int s = 0; s < 8; s++) acc[s] = bb;
        for (int k = 0; k < 256; k++) {
            float wv = w2[k * 256 + tid];
#pragma unroll
            for (int s = 0; s < 8; s++) acc[s] += mid[s * 256 + k] * wv;
        }
#pragma unroll
        for (int s = 0; s < 8; s++) {
            float res = hn[s * 256 + tid] + fmaxf(acc[s], 0.f);
            g_slots[b * 2048 + s * 256 + tid] = res;
            if (wout) out[b * 2048 + s * 256 + tid] = res;
        }
    }
}

// ---------------- host launcher ----------------
extern "C" void kernel_launch(void* const* d_in, const int* in_sizes, int n_in,
                              void* d_out, int out_size) {
    const float* x          = (const float*)d_in[0];
    const float* eps_noise  = (const float*)d_in[1];
    const float* pos_w      = (const float*)d_in[2];
    const float* pos_b      = (const float*)d_in[3];
    const float* enc_g      = (const float*)d_in[4];
    const float* enc_b      = (const float*)d_in[5];
    const float* fm_w1      = (const float*)d_in[6];
    const float* fm_b1      = (const float*)d_in[7];
    const float* fm_w2      = (const float*)d_in[8];
    const float* fm_b2      = (const float*)d_in[9];
    const float* in_g       = (const float*)d_in[10];
    const float* in_b       = (const float*)d_in[11];
    const float* q_w        = (const float*)d_in[12];
    const float* q_b        = (const float*)d_in[13];
    const float* k_w        = (const float*)d_in[14];
    const float* k_b        = (const float*)d_in[15];
    const float* v_w        = (const float*)d_in[16];
    const float* v_b        = (const float*)d_in[17];
    const float* gru_wih    = (const float*)d_in[18];
    const float* gru_whh    = (const float*)d_in[19];
    const float* gru_bih    = (const float*)d_in[20];
    const float* gru_bhh    = (const float*)d_in[21];
    const float* pre_g      = (const float*)d_in[22];
    const float* pre_b      = (const float*)d_in[23];
    const float* st_w1      = (const float*)d_in[24];
    const float* st_b1      = (const float*)d_in[25];
    const float* st_w2      = (const float*)d_in[26];
    const float* st_b2      = (const float*)d_in[27];
    const float* slot_g     = (const float*)d_in[28];
    const float* slot_b     = (const float*)d_in[29];
    const float* slots_loc  = (const float*)d_in[30];
    const float* slots_lsc  = (const float*)d_in[31];

    const int ENC_SMEM = ENC_SMEM_MAX;       // 207872 (covers both encoder variants)
    const int ATTN_SMEM = ATTN_SMEM_BYTES;   // 61248

    cudaFuncSetAttribute(k_encoder, cudaFuncAttributeMaxDynamicSharedMemorySize, ENC_SMEM);
    cudaFuncSetAttribute(k_attn, cudaFuncAttributeMaxDynamicSharedMemorySize, ATTN_SMEM);

    // launch order keeps k_encoder as the 4th launch (ncu captures launch #4)
    k_stats<<<dim3(32, 64), 256>>>(x, pos_w, pos_b);
    k_stats2<<<32, 64>>>();
    k_cvtW2<<<2176, 256>>>(fm_w1, fm_w2, k_w, v_w, enc_g, enc_b);
    k_encoder<<<dim3(32, 32), 512, ENC_SMEM>>>(x, pos_w, pos_b, fm_b1, fm_b2, in_g, in_b,
                                               k_b, v_b);
    k_init<<<32, 256>>>(eps_noise, slots_loc, slots_lsc);
    for (int it = 0; it < 3; it++) {
        k_q<<<32, 256>>>(q_w, q_b, slot_g, slot_b);
        k_attn<<<dim3(32, 32), 256, ATTN_SMEM>>>();
        k_upd<<<32, 256>>>();
        k_gates<<<dim3(32, 3), 256>>>(gru_wih, gru_whh, gru_bih, gru_bhh);
        k_gru2<<<32, 256>>>(pre_g, pre_b, st_w1, st_b1, st_w2, st_b2,
                            (float*)d_out, it == 2 ? 1 : 0);
    }
}

// round 14
// speedup vs baseline: 1.1213x; 1.0500x over previous
#include <cuda_runtime.h>
#include <cuda_bf16.h>
#include <math.h>
#include <stdint.h>

#define NB 32
#define ND 256
#define NTOK 4096
#define NSLOT 8

// ---------------- scratch (device globals; no allocation allowed) ----------------
__device__ uint32_t g_kb[NB * NTOK * 128];     // bf16-pair packed k: 67 MB
__device__ uint32_t g_vb[NB * NTOK * 128];     // bf16-pair packed v: 67 MB
__device__ uint32_t g_wp[4][ND * 128];         // n-major bf16-pair weights: [n][kpair]
__device__ float g_egT[ND * NTOK];             // transposed enc_g [d][tok]
__device__ float g_ebT[ND * NTOK];             // transposed enc_b [d][tok]
__device__ float g_stats_part[NB * 64 * 2];
__device__ float g_stats[NB * 2];              // mean, rstd per batch
__device__ float g_slots[NB * NSLOT * ND];
__device__ float g_q[NB * NSLOT * ND];
__device__ float g_upd_part[NB * 32 * NSLOT * ND];
__device__ float g_psum_part[NB * 32 * NSLOT];
__device__ float g_upd[NB * NSLOT * ND];
__device__ float g_gi[NB * NSLOT * 768];
__device__ float g_gh[NB * NSLOT * 768];

__device__ __forceinline__ float warp_sum(float v) {
#pragma unroll
    for (int o = 16; o; o >>= 1) v += __shfl_xor_sync(0xffffffffu, v, o);
    return v;
}

__device__ __forceinline__ uint32_t packbf(float a, float b) {
    __nv_bfloat162 h = __floats2bfloat162_rn(a, b);  // .x = a (low), .y = b (high)
    return *(uint32_t*)&h;
}
__device__ __forceinline__ float2 unpackbf(uint32_t u) {
    __nv_bfloat162 h = *(__nv_bfloat162*)&u;
    return __bfloat1622float2(h);
}

// ---------------- K0: per-batch sum / sumsq of h = x + pos (exact fp32) ----------------
__global__ void __launch_bounds__(256) k_stats(const float* __restrict__ x,
                                               const float* __restrict__ pos_w,
                                               const float* __restrict__ pos_b) {
    int b = blockIdx.x, c = blockIdx.y, tid = threadIdx.x;
    float s = 0.f, q = 0.f;
    int base = c * 16384;
    for (int e = base + tid; e < base + 16384; e += 256) {
        int d = e >> 12;
        int ij = e & 4095;
        int ti = ij >> 6, tj = ij & 63;
        float fi = ti * (1.0f / 63.0f), fj = tj * (1.0f / 63.0f);
        float p = fi * pos_w[d] + fj * pos_w[256 + d] + (1.0f - fi) * pos_w[512 + d] +
                  (1.0f - fj) * pos_w[768 + d] + pos_b[d];
        float v = x[b * 1048576 + e] + p;
        s += v;
        q += v * v;
    }
    s = warp_sum(s);
    q = warp_sum(q);
    __shared__ float rs[8], rq[8];
    int w = tid >> 5, lane = tid & 31;
    if (lane == 0) { rs[w] = s; rq[w] = q; }
    __syncthreads();
    if (tid == 0) {
        float S = 0.f, Q = 0.f;
#pragma unroll
        for (int i = 0; i < 8; i++) { S += rs[i]; Q += rq[i]; }
        g_stats_part[(b * 64 + c) * 2 + 0] = S;
        g_stats_part[(b * 64 + c) * 2 + 1] = Q;
    }
}

// ---------------- K0b: finalize per-batch stats (parallel tree in double) ----------------
__global__ void __launch_bounds__(64) k_stats2() {
    __shared__ double rs[64], rq[64];
    int b = blockIdx.x, tid = threadIdx.x;
    rs[tid] = (double)g_stats_part[(b * 64 + tid) * 2 + 0];
    rq[tid] = (double)g_stats_part[(b * 64 + tid) * 2 + 1];
    __syncthreads();
#pragma unroll
    for (int o = 32; o; o >>= 1) {
        if (tid < o) {
            rs[tid] += rs[tid + o];
            rq[tid] += rq[tid + o];
        }
        __syncthreads();
    }
    if (tid == 0) {
        double N = 1048576.0;
        double mu = rs[0] / N;
        double var = rq[0] / N - mu * mu;
        g_stats[b * 2 + 0] = (float)mu;
        g_stats[b * 2 + 1] = (float)(1.0 / sqrt(var + 1e-5));
    }
}

// ------- weight pre-pack to n-major bf16 pairs + enc_g/enc_b transpose (merged) -------
__global__ void __launch_bounds__(256) k_cvtW2(const float* __restrict__ w1,
                                               const float* __restrict__ w2,
                                               const float* __restrict__ wk,
                                               const float* __restrict__ wv,
                                               const float* __restrict__ eg,
                                               const float* __restrict__ eb) {
    __shared__ uint32_t tile[32][33];
    int bid = blockIdx.x;
    int tx = threadIdx.x & 31, ty = threadIdx.x >> 5;  // 32 x 8
    if (bid < 128) {
        int m = bid >> 5, rem = bid & 31;
        int kpt = rem >> 3, nt = rem & 7;
        const float* srcs[4] = {w1, w2, wk, wv};
        const float* w = srcs[m];
#pragma unroll
        for (int i = 0; i < 4; i++) {
            int kp = kpt * 32 + ty + 8 * i;
            int n = nt * 32 + tx;
            tile[ty + 8 * i][tx] = packbf(w[(2 * kp) * 256 + n], w[(2 * kp + 1) * 256 + n]);
        }
        __syncthreads();
#pragma unroll
        for (int i = 0; i < 4; i++) {
            int n = nt * 32 + ty + 8 * i;
            int kp = kpt * 32 + tx;
            g_wp[m][n * 128 + kp] = tile[tx][ty + 8 * i];
        }
    } else {
        int pid = bid - 128;                       // 0..2047
        int tok0 = (pid & 127) * 32;
        int d0 = ((pid >> 7) & 7) * 32;
        int z = pid >> 10;
        const float* src = z ? eb : eg;
        float* dst = z ? g_ebT : g_egT;
#pragma unroll
        for (int i = 0; i < 4; i++)
            tile[ty + 8 * i][tx] =
                __float_as_uint(src[(tok0 + ty + 8 * i) * 256 + d0 + tx]);
        __syncthreads();
#pragma unroll
        for (int i = 0; i < 4; i++)
            dst[(d0 + ty + 8 * i) * 4096 + tok0 + tx] =
                __uint_as_float(tile[tx][ty + 8 * i]);
    }
}

// ---------------- shared helpers (both encoder variants) ----------------
__device__ __forceinline__ uint32_t swz16(uint32_t o) { return o ^ ((o >> 3) & 0x70); }

__device__ __forceinline__ void mma16bf(float* c, const uint32_t a[4], uint32_t b0,
                                        uint32_t b1) {
    asm volatile(
        "mma.sync.aligned.m16n8k16.row.col.f32.bf16.bf16.f32 "
        "{%0,%1,%2,%3}, {%4,%5,%6,%7}, {%8,%9}, {%0,%1,%2,%3};"
        : "+f"(c[0]), "+f"(c[1]), "+f"(c[2]), "+f"(c[3])
        : "r"(a[0]), "r"(a[1]), "r"(a[2]), "r"(a[3]), "r"(b0), "r"(b1));
}

__device__ __forceinline__ void ldsm4(uint32_t f[4], uint32_t addr) {
    asm volatile("ldmatrix.sync.aligned.m8n8.x4.shared.b16 {%0,%1,%2,%3}, [%4];"
                 : "=r"(f[0]), "=r"(f[1]), "=r"(f[2]), "=r"(f[3])
                 : "r"(addr));
}

#if !defined(__CUDA_ARCH__) || defined(__CUDA_ARCH_FEAT_SM103_ALL)
// ---------------- tcgen05 helpers (sm_103a-only compilation pass) ----------------
static constexpr uint64_t DESC_BASE_SW128 =
    (2ull << 61) | (1ull << 46) | (64ull << 32) | (1ull << 16);

__device__ __forceinline__ uint64_t mk_desc(uint32_t addr) {
    return DESC_BASE_SW128 | ((uint64_t)(addr >> 4) & 0x3FFF);
}

// idesc kind::f16: F32 acc, a=BF16, b=BF16, N=128, M=128
#define ENC_IDESC ((1u << 4) | (1u << 7) | (1u << 10) | (16u << 17) | (8u << 24))

__device__ __forceinline__ bool elect1() {
    uint32_t p;
    asm volatile(
        "{\n\t.reg .pred p;\n\telect.sync _|p, 0xFFFFFFFF;\n\tselp.b32 %0, 1, 0, p;\n\t}"
        : "=r"(p));
    return p != 0;
}

__device__ __forceinline__ void mma_f16_ss(uint32_t d_tmem, uint64_t a_desc,
                                           uint64_t b_desc, uint32_t idesc, bool accum) {
    uint32_t en = accum ? 1u : 0u;
    asm volatile(
        "{\n\t"
        ".reg .pred p;\n\t"
        "setp.ne.u32 p, %5, 0;\n\t"
        "tcgen05.mma.cta_group::1.kind::f16 [%0], %1, %2, %3, {%4, %4, %4, %4}, p;\n\t"
        "}"
        :: "r"(d_tmem), "l"(a_desc), "l"(b_desc), "r"(idesc), "r"(0u), "r"(en)
        : "memory");
}

__device__ __forceinline__ void mbar_wait(uint32_t mbar, uint32_t par) {
    uint32_t done;
    asm volatile(
        "{\n\t.reg .pred p;\n\t"
        "mbarrier.try_wait.parity.acquire.cta.shared::cta.b64 p, [%1], %2;\n\t"
        "selp.b32 %0, 1, 0, p;\n\t}"
        : "=r"(done) : "r"(mbar), "r"(par) : "memory");
    while (!done) {
        asm volatile(
            "{\n\t.reg .pred p;\n\t"
            "mbarrier.try_wait.parity.acquire.cta.shared::cta.b64 p, [%1], %2, 0x989680;\n\t"
            "selp.b32 %0, 1, 0, p;\n\t}"
            : "=r"(done) : "r"(mbar), "r"(par) : "memory");
    }
}

__device__ __forceinline__ void tmem_ld32(uint32_t* r, uint32_t taddr) {
    asm volatile(
        "tcgen05.ld.sync.aligned.32x32b.x32.b32 "
        "{%0, %1, %2, %3, %4, %5, %6, %7, "
        " %8, %9, %10, %11, %12, %13, %14, %15, "
        " %16, %17, %18, %19, %20, %21, %22, %23, "
        " %24, %25, %26, %27, %28, %29, %30, %31}, [%32];"
        : "=r"(r[0]),  "=r"(r[1]),  "=r"(r[2]),  "=r"(r[3]),
          "=r"(r[4]),  "=r"(r[5]),  "=r"(r[6]),  "=r"(r[7]),
          "=r"(r[8]),  "=r"(r[9]),  "=r"(r[10]), "=r"(r[11]),
          "=r"(r[12]), "=r"(r[13]), "=r"(r[14]), "=r"(r[15]),
          "=r"(r[16]), "=r"(r[17]), "=r"(r[18]), "=r"(r[19]),
          "=r"(r[20]), "=r"(r[21]), "=r"(r[22]), "=r"(r[23]),
          "=r"(r[24]), "=r"(r[25]), "=r"(r[26]), "=r"(r[27]),
          "=r"(r[28]), "=r"(r[29]), "=r"(r[30]), "=r"(r[31])
        : "r"(taddr));
}
#endif  // tcgen05 helpers

// tcgen05 smem layout (bytes, relative to 1024-aligned base)
#define ENC_PW 1024
#define ENC_PB 5120
#define ENC_A 6144                      // 128 rows x 256 bf16, SW128 blocked (64 KB)
#define ENC_B 71680                     // 256 rows x 256 bf16, SW128 blocked (128 KB)
// fallback (ldmatrix) layout constants
#define FB_A_ST 132
#define FB_W_ST 132
#define FB_A_U32 (128 * FB_A_ST)
#define FB_WBUF_U32 (256 * FB_W_ST)
#define ENC_SMEM_MAX 207872             // max(tcgen05 203776, fallback 207872)

#if defined(__CUDA_ARCH__) && !defined(__CUDA_ARCH_FEAT_SM103_ALL)
// fallback GEMM (ldmatrix path) — compiled only for the portable-PTX pass
__device__ __forceinline__ void fb_run_gemm(const uint32_t* __restrict__ Wg,
                                            uint32_t a_sh, uint32_t w_sh,
                                            uint32_t rowA0, uint32_t rowA1,
                                            const uint32_t rowB[4],
                                            float acc[2][8][4], int tid) {
#pragma unroll
    for (int mt = 0; mt < 2; mt++)
#pragma unroll
        for (int nt = 0; nt < 8; nt++)
#pragma unroll
            for (int e = 0; e < 4; e++) acc[mt][nt][e] = 0.f;
#pragma unroll
    for (int h = 0; h < 2; h++) {
#pragma unroll
        for (int q = 0; q < 8; q++) {
            int idx = q * 512 + tid;
            int n = idx >> 4;
            int col = h * 64 + (idx & 15) * 4;
            uint32_t dst = w_sh + (uint32_t)((n * FB_W_ST + col) * 4);
            const uint32_t* src = Wg + n * 128 + col;
            asm volatile("cp.async.cg.shared.global [%0], [%1], 16;" ::"r"(dst), "l"(src));
        }
        asm volatile("cp.async.commit_group;");
    }
    asm volatile("cp.async.wait_group 1;");
    __syncthreads();
#pragma unroll
    for (int kc = 0; kc < 8; kc++) {
        uint32_t k0p = kc * 8;
        uint32_t fa0[4], fa1[4];
        ldsm4(fa0, a_sh + (rowA0 + k0p) * 4);
        ldsm4(fa1, a_sh + (rowA1 + k0p) * 4);
#pragma unroll
        for (int ntp = 0; ntp < 4; ntp++) {
            uint32_t fb[4];
            ldsm4(fb, w_sh + (rowB[ntp] + k0p) * 4);
            mma16bf(acc[0][2 * ntp], fa0, fb[0], fb[1]);
            mma16bf(acc[1][2 * ntp], fa1, fb[0], fb[1]);
            mma16bf(acc[0][2 * ntp + 1], fa0, fb[2], fb[3]);
            mma16bf(acc[1][2 * ntp + 1], fa1, fb[2], fb[3]);
        }
    }
    asm volatile("cp.async.wait_group 0;");
    __syncthreads();
#pragma unroll
    for (int kc = 8; kc < 16; kc++) {
        uint32_t k0p = kc * 8;
        uint32_t fa0[4], fa1[4];
        ldsm4(fa0, a_sh + (rowA0 + k0p) * 4);
        ldsm4(fa1, a_sh + (rowA1 + k0p) * 4);
#pragma unroll
        for (int ntp = 0; ntp < 4; ntp++) {
            uint32_t fb[4];
            ldsm4(fb, w_sh + (rowB[ntp] + k0p) * 4);
            mma16bf(acc[0][2 * ntp], fa0, fb[0], fb[1]);
            mma16bf(acc[1][2 * ntp], fa1, fb[0], fb[1]);
            mma16bf(acc[0][2 * ntp + 1], fa0, fb[2], fb[3]);
            mma16bf(acc[1][2 * ntp + 1], fa1, fb[2], fb[3]);
        }
    }
    __syncthreads();
}
#endif

// ---------------- K1: fused bf16 encoder (512 threads; tcgen05 on sm_103a) ----------------
__global__ void __launch_bounds__(512, 1) __cluster_dims__(1, 1, 1) k_encoder(
    const float* __restrict__ x, const float* __restrict__ pos_w,
    const float* __restrict__ pos_b, const float* __restrict__ fm_b1,
    const float* __restrict__ fm_b2, const float* __restrict__ in_g,
    const float* __restrict__ in_b, const float* __restrict__ k_b,
    const float* __restrict__ v_b) {
#if !defined(__CUDA_ARCH__) || defined(__CUDA_ARCH_FEAT_SM103_ALL)
    // ================== tcgen05 path ==================
    extern __shared__ char smraw[];
    uint32_t smb_raw = (uint32_t)__cvta_generic_to_shared(smraw);
    uint32_t smb = (smb_raw + 1023u) & ~1023u;
    char* smc = smraw + (smb - smb_raw);
    float* pw = (float*)(smc + ENC_PW);
    float* pb = (float*)(smc + ENC_PB);

    int b = blockIdx.y, t0 = blockIdx.x * 128;
    int tid = threadIdx.x, wid = tid >> 5, lane = tid & 31;

    if (tid == 0)
        asm volatile("mbarrier.init.shared.b64 [%0], %1;" ::"r"(smb + 8), "r"(1u)
                     : "memory");
    if (wid == 0)
        asm volatile(
            "tcgen05.alloc.cta_group::1.sync.aligned.shared::cta.b32 [%0], %1;" ::"r"(smb),
            "r"(256u)
            : "memory");

    auto stageB = [&](const uint32_t* __restrict__ Wg) {
#pragma unroll
        for (int q = 0; q < 16; q++) {
            int idx = q * 512 + tid;              // 0..8191 16B granules
            int n = idx >> 5, gg = idx & 31;
            uint32_t dst = smb + ENC_B + (uint32_t)(gg >> 3) * 32768u +
                           swz16((uint32_t)(n * 128 + (gg & 7) * 16));
            const uint32_t* src = Wg + n * 128 + gg * 4;
            asm volatile("cp.async.cg.shared.global [%0], [%1], 16;" ::"r"(dst), "l"(src));
        }
        asm volatile("cp.async.commit_group;" ::: "memory");
    };
    stageB(g_wp[0]);

    for (int i = tid; i < 1024; i += 512) pw[i] = pos_w[i];
    if (tid < 256) pb[tid] = pos_b[tid];
    __syncthreads();

    uint32_t tmem_base;
    asm volatile("ld.shared.b32 %0, [%1];" : "=r"(tmem_base) : "r"(smb));
    float mean = g_stats[b * 2 + 0], rstd = g_stats[b * 2 + 1];

    // fused load (COALESCED): warp owns one d per iter, lanes span 32 consecutive tokens.
    // x / egT / ebT are all [d][tok] -> every global load is a full 128B warp transaction.
    // Transpose into the tok-major swizzled A tile via u16 smem stores.
    {
#pragma unroll 2
        for (int it = 0; it < 16; it++) {
            int d = wid * 16 + it;                 // 16 warps x 16 = 256 d
            float pwa = pw[d], pwb = pw[256 + d], pwc = pw[512 + d], pwd = pw[768 + d];
            float pbb = pb[d];
            int qblk = d >> 6;                     // atom-col block
            uint32_t c2 = (uint32_t)((d & 63) * 2);
            const float* xrow = x + ((size_t)(b * 256 + d)) * 4096 + t0;
            const float* erow = g_egT + (size_t)d * 4096 + t0;
            const float* crow = g_ebT + (size_t)d * 4096 + t0;
#pragma unroll
            for (int jj = 0; jj < 4; jj++) {
                int tok_l = jj * 32 + lane;
                int tok = t0 + tok_l;
                int ti = tok >> 6, tj = tok & 63;
                float fi = ti * (1.0f / 63.0f), fj = tj * (1.0f / 63.0f);
                float pos = fi * pwa + fj * pwb + (1.0f - fi) * pwc + (1.0f - fj) * pwd + pbb;
                float v = (xrow[tok_l] + pos - mean) * rstd * erow[tok_l] + crow[tok_l];
                __nv_bfloat16 hv = __float2bfloat16(v);
                *(uint16_t*)(smc + ENC_A + qblk * 16384 +
                             swz16((uint32_t)(tok_l * 128) + c2)) = *(uint16_t*)&hv;
            }
        }
    }

    int sub = wid & 3, cg = wid >> 2;
    int m = sub * 32 + lane;

#pragma unroll 1
    for (int g = 0; g < 4; g++) {
        asm volatile("fence.proxy.async.shared::cta;" ::: "memory");
        asm volatile("cp.async.wait_group 0;" ::: "memory");
        __syncthreads();
        if (wid == 0 && elect1()) {
            uint64_t a0 = mk_desc(smb + ENC_A);
            uint64_t b0 = mk_desc(smb + ENC_B);
#pragma unroll
            for (int nh = 0; nh < 2; nh++) {
#pragma unroll
                for (int s = 0; s < 16; s++) {
                    uint64_t ad = a0 + (uint64_t)((s >> 2) * 1024 + (s & 3) * 2);
                    uint64_t bd =
                        b0 + (uint64_t)(nh * 1024 + (s >> 2) * 2048 + (s & 3) * 2);
                    mma_f16_ss(tmem_base + nh * 128, ad, bd, ENC_IDESC, s > 0);
                }
            }
            asm volatile(
                "tcgen05.commit.cta_group::1.mbarrier::arrive::one.shared::cluster.b64 "
                "[%0];" ::"r"(smb + 8)
                : "memory");
        }
        mbar_wait(smb + 8, (uint32_t)(g & 1));
        asm volatile("tcgen05.fence::after_thread_sync;" ::: "memory");

        if (g == 0) stageB(g_wp[1]);
        else if (g == 1) stageB(g_wp[2]);
        else if (g == 2) stageB(g_wp[3]);

        uint32_t dr[64];
        tmem_ld32(dr, tmem_base + cg * 64);
        tmem_ld32(dr + 32, tmem_base + cg * 64 + 32);
        asm volatile("tcgen05.wait::ld.sync.aligned;" ::: "memory");

        if (g < 2) {
            const float* bias = (g == 0) ? fm_b1 : fm_b2;
#pragma unroll
            for (int j = 0; j < 32; j++) {
                float2 bb = *(const float2*)&bias[64 * cg + 2 * j];
                float v0 = fmaxf(__uint_as_float(dr[2 * j]) + bb.x, 0.f);
                float v1 = fmaxf(__uint_as_float(dr[2 * j + 1]) + bb.y, 0.f);
                *(uint32_t*)(smc + ENC_A + cg * 16384 +
                             swz16((uint32_t)(m * 128 + j * 4))) = packbf(v0, v1);
            }
            if (g == 1) {
                __syncthreads();
                for (int rr = 0; rr < 8; rr++) {
                    int r = wid * 8 + rr;
                    float2 vv[4];
                    float s1 = 0.f, s2 = 0.f;
#pragma unroll
                    for (int u = 0; u < 4; u++) {
                        uint32_t val = *(uint32_t*)(smc + ENC_A + u * 16384 +
                                                    swz16((uint32_t)(r * 128 + lane * 4)));
                        vv[u] = unpackbf(val);
                        s1 += vv[u].x + vv[u].y;
                        s2 += vv[u].x * vv[u].x + vv[u].y * vv[u].y;
                    }
                    s1 = warp_sum(s1);
                    s2 = warp_sum(s2);
                    float mu = s1 * (1.0f / 256.0f);
                    float rsd = rsqrtf(s2 * (1.0f / 256.0f) - mu * mu + 1e-5f);
#pragma unroll
                    for (int u = 0; u < 4; u++) {
                        int p = lane + 32 * u;
                        float2 ig = *(const float2*)&in_g[2 * p];
                        float2 ib = *(const float2*)&in_b[2 * p];
                        *(uint32_t*)(smc + ENC_A + u * 16384 +
                                     swz16((uint32_t)(r * 128 + lane * 4))) =
                            packbf((vv[u].x - mu) * rsd * ig.x + ib.x,
                                   (vv[u].y - mu) * rsd * ig.y + ib.y);
                    }
                }
            }
        } else {
            const float* bias = (g == 2) ? k_b : v_b;
            uint32_t* gout = (g == 2) ? g_kb : g_vb;
            uint32_t* dst = gout + ((size_t)(b * 4096 + t0 + m)) * 128 + cg * 32;
#pragma unroll
            for (int j = 0; j < 16; j++) {
                float2 bb0 = *(const float2*)&bias[64 * cg + 4 * j];
                float2 bb1 = *(const float2*)&bias[64 * cg + 4 * j + 2];
                uint2 vv;
                vv.x = packbf(__uint_as_float(dr[4 * j]) + bb0.x,
                              __uint_as_float(dr[4 * j + 1]) + bb0.y);
                vv.y = packbf(__uint_as_float(dr[4 * j + 2]) + bb1.x,
                              __uint_as_float(dr[4 * j + 3]) + bb1.y);
                *(uint2*)(dst + 2 * j) = vv;
            }
        }
    }
    __syncthreads();
    if (tid == 0)
        asm volatile("mbarrier.inval.shared.b64 [%0];" ::"r"(smb + 8) : "memory");
    if (wid == 0)
        asm volatile("tcgen05.dealloc.cta_group::1.sync.aligned.b32 %0, %1;" ::"r"(
                         tmem_base),
                     "r"(256u));
#else
    // ================== fallback ldmatrix path (portable PTX pass) ==================
    extern __shared__ char smraw[];
    uint32_t* A = (uint32_t*)smraw;
    uint32_t* Wbuf = A + FB_A_U32;
    float* pw = (float*)(Wbuf + FB_WBUF_U32);
    float* pb = pw + 1024;

    int b = blockIdx.y, t0 = blockIdx.x * 128;
    int tid = threadIdx.x, wid = tid >> 5, lane = tid & 31;
    int wm = wid & 3, wn = wid >> 2;
    int g = lane >> 2, t = lane & 3;

    uint32_t a_sh = (uint32_t)__cvta_generic_to_shared(A);
    uint32_t w_sh = (uint32_t)__cvta_generic_to_shared(Wbuf);

    int sub = lane >> 3, wi = lane & 7;
    uint32_t rowA0 =
        (uint32_t)((wm * 32 + 0 + (sub & 1) * 8 + wi) * FB_A_ST + (sub >> 1) * 4);
    uint32_t rowA1 =
        (uint32_t)((wm * 32 + 16 + (sub & 1) * 8 + wi) * FB_A_ST + (sub >> 1) * 4);
    uint32_t rowB[4];
#pragma unroll
    for (int ntp = 0; ntp < 4; ntp++)
        rowB[ntp] = (uint32_t)((wn * 64 + ntp * 16 + (sub >> 1) * 8 + wi) * FB_W_ST +
                               (sub & 1) * 4);

    for (int i = tid; i < 1024; i += 512) pw[i] = pos_w[i];
    if (tid < 256) pb[tid] = pos_b[tid];
    float mean = g_stats[b * 2 + 0], rstd = g_stats[b * 2 + 1];
    __syncthreads();

    {
        int r2 = tid >> 2, qq = tid & 3;
        int tok = t0 + r2;
        int ti = tok >> 6, tj = tok & 63;
        float fi = ti * (1.0f / 63.0f), fj = tj * (1.0f / 63.0f);
#pragma unroll 4
        for (int i = 0; i < 32; i++) {
            int p = qq * 32 + i;
            int d0 = 2 * p, d1 = d0 + 1;
            float p0 = fi * pw[d0] + fj * pw[256 + d0] + (1.0f - fi) * pw[512 + d0] +
                       (1.0f - fj) * pw[768 + d0] + pb[d0];
            float p1 = fi * pw[d1] + fj * pw[256 + d1] + (1.0f - fi) * pw[512 + d1] +
                       (1.0f - fj) * pw[768 + d1] + pb[d1];
            float x0 = x[(b * 256 + d0) * 4096 + tok];
            float x1 = x[(b * 256 + d1) * 4096 + tok];
            float e0 = g_egT[d0 * 4096 + tok], e1 = g_egT[d1 * 4096 + tok];
            float c0 = g_ebT[d0 * 4096 + tok], c1 = g_ebT[d1 * 4096 + tok];
            A[r2 * FB_A_ST + p] =
                packbf((x0 + p0 - mean) * rstd * e0 + c0, (x1 + p1 - mean) * rstd * e1 + c1);
        }
    }
    __syncthreads();

    float acc[2][8][4];

    fb_run_gemm(g_wp[0], a_sh, w_sh, rowA0, rowA1, rowB, acc, tid);
#pragma unroll
    for (int nt = 0; nt < 8; nt++) {
        int c = wn * 64 + nt * 8 + 2 * t;
        int p = c >> 1;
        float2 bb = *(const float2*)&fm_b1[c];
#pragma unroll
        for (int mt = 0; mt < 2; mt++) {
            int r = wm * 32 + mt * 16 + g;
            float* a = acc[mt][nt];
            A[r * FB_A_ST + p] = packbf(fmaxf(a[0] + bb.x, 0.f), fmaxf(a[1] + bb.y, 0.f));
            A[(r + 8) * FB_A_ST + p] =
                packbf(fmaxf(a[2] + bb.x, 0.f), fmaxf(a[3] + bb.y, 0.f));
        }
    }
    __syncthreads();

    fb_run_gemm(g_wp[1], a_sh, w_sh, rowA0, rowA1, rowB, acc, tid);
#pragma unroll
    for (int nt = 0; nt < 8; nt++) {
        int c = wn * 64 + nt * 8 + 2 * t;
        int p = c >> 1;
        float2 bb = *(const float2*)&fm_b2[c];
#pragma unroll
        for (int mt = 0; mt < 2; mt++) {
            int r = wm * 32 + mt * 16 + g;
            float* a = acc[mt][nt];
            A[r * FB_A_ST + p] = packbf(fmaxf(a[0] + bb.x, 0.f), fmaxf(a[1] + bb.y, 0.f));
            A[(r + 8) * FB_A_ST + p] =
                packbf(fmaxf(a[2] + bb.x, 0.f), fmaxf(a[3] + bb.y, 0.f));
        }
    }
    __syncthreads();

    for (int rr = 0; rr < 8; rr++) {
        int r = wid * 8 + rr;
        float2 vv[4];
        float s1 = 0.f, s2 = 0.f;
#pragma unroll
        for (int u = 0; u < 4; u++) {
            vv[u] = unpackbf(A[r * FB_A_ST + lane + 32 * u]);
            s1 += vv[u].x + vv[u].y;
            s2 += vv[u].x * vv[u].x + vv[u].y * vv[u].y;
        }
        s1 = warp_sum(s1);
        s2 = warp_sum(s2);
        float mu = s1 * (1.0f / 256.0f);
        float rsd = rsqrtf(s2 * (1.0f / 256.0f) - mu * mu + 1e-5f);
#pragma unroll
        for (int u = 0; u < 4; u++) {
            int p = lane + 32 * u;
            float2 ig = *(const float2*)&in_g[2 * p];
            float2 ib = *(const float2*)&in_b[2 * p];
            A[r * FB_A_ST + p] = packbf((vv[u].x - mu) * rsd * ig.x + ib.x,
                                        (vv[u].y - mu) * rsd * ig.y + ib.y);
        }
    }
    __syncthreads();

    fb_run_gemm(g_wp[2], a_sh, w_sh, rowA0, rowA1, rowB, acc, tid);
#pragma unroll
    for (int nt = 0; nt < 8; nt++) {
        int c = wn * 64 + nt * 8 + 2 * t;
        int p = c >> 1;
        float2 bb = *(const float2*)&k_b[c];
#pragma unroll
        for (int mt = 0; mt < 2; mt++) {
            int r = wm * 32 + mt * 16 + g;
            float* a = acc[mt][nt];
            g_kb[((size_t)(b * 4096 + t0 + r)) * 128 + p] = packbf(a[0] + bb.x, a[1] + bb.y);
            g_kb[((size_t)(b * 4096 + t0 + r + 8)) * 128 + p] =
                packbf(a[2] + bb.x, a[3] + bb.y);
        }
    }

    fb_run_gemm(g_wp[3], a_sh, w_sh, rowA0, rowA1, rowB, acc, tid);
#pragma unroll
    for (int nt = 0; nt < 8; nt++) {
        int c = wn * 64 + nt * 8 + 2 * t;
        int p = c >> 1;
        float2 bb = *(const float2*)&v_b[c];
#pragma unroll
        for (int mt = 0; mt < 2; mt++) {
            int r = wm * 32 + mt * 16 + g;
            float* a = acc[mt][nt];
            g_vb[((size_t)(b * 4096 + t0 + r)) * 128 + p] = packbf(a[0] + bb.x, a[1] + bb.y);
            g_vb[((size_t)(b * 4096 + t0 + r + 8)) * 128 + p] =
                packbf(a[2] + bb.x, a[3] + bb.y);
        }
    }
#endif
}

// ---------------- slot init ----------------
__global__ void k_init(const float* __restrict__ eps, const float* __restrict__ loc,
                       const float* __restrict__ lsc) {
    int b = blockIdx.x, tid = threadIdx.x;
    for (int idx = tid; idx < 2048; idx += 256) {
        int d = idx & 255;
        g_slots[b * 2048 + idx] = loc[d] + __expf(lsc[d]) * eps[b * 2048 + idx];
    }
}

// ---------------- per-iter: slot LN + q projection (scaled, fp32) ----------------
__global__ void __launch_bounds__(256) k_q(const float* __restrict__ q_w,
                                           const float* __restrict__ q_b,
                                           const float* __restrict__ slot_g,
                                           const float* __restrict__ slot_b) {
    __shared__ float ss[8 * 256];
    int b = blockIdx.x, tid = threadIdx.x, w = tid >> 5, lane = tid & 31;
    {
        float vv[8];
        float s1 = 0.f, s2 = 0.f;
#pragma unroll
        for (int u = 0; u < 8; u++) {
            vv[u] = g_slots[(b * 8 + w) * 256 + lane + 32 * u];
            s1 += vv[u];
            s2 += vv[u] * vv[u];
        }
        s1 = warp_sum(s1);
        s2 = warp_sum(s2);
        float mu = s1 * (1.0f / 256.0f);
        float rsd = rsqrtf(s2 * (1.0f / 256.0f) - mu * mu + 1e-5f);
#pragma unroll
        for (int u = 0; u < 8; u++) {
            int d = lane + 32 * u;
            ss[w * 256 + d] = (vv[u] - mu) * rsd * slot_g[d] + slot_b[d];
        }
    }
    __syncthreads();
    float acc[8];
#pragma unroll
    for (int i = 0; i < 8; i++) acc[i] = 0.f;
    for (int k = 0; k < 256; k++) {
        float wv = q_w[k * 256 + tid];
#pragma unroll
        for (int i = 0; i < 8; i++) acc[i] += ss[i * 256 + k] * wv;
    }
    float qb = q_b[tid];
#pragma unroll
    for (int i = 0; i < 8; i++)
        g_q[(b * 8 + i) * 256 + tid] = (acc[i] + qb) * 0.0625f;  // * D^-0.5
}

// ---------------- per-iter: streaming attention (bf16 k/v, pipelined) ----------------
#define CH 16
#define KVSTu 136                       // u32 per row, halves at 0 / 68
#define STG_U32 (2 * CH * KVSTu)        // 4352: k then v
#define QST 264                         // floats, halves at 0 / 132
#define ATTN_SMEM_BYTES (3 * STG_U32 * 4 + (8 * QST + CH * 9) * 4)

__global__ void __launch_bounds__(256) k_attn() {
    extern __shared__ char smraw[];
    uint32_t* stg = (uint32_t*)smraw;
    float* qs = (float*)(stg + 3 * STG_U32);
    float* dt = qs + 8 * QST;
    int tile = blockIdx.x, b = blockIdx.y;
    int tid = threadIdx.x;
    uint32_t smbase = (uint32_t)__cvta_generic_to_shared(stg);

    // stage q with h-split (float f -> +4 if f>=128)
    for (int i = tid; i < 2048; i += 256) {
        int s = i >> 8, f = i & 255;
        qs[s * QST + f + ((f >= 128) ? 4 : 0)] = g_q[b * 2048 + i];
    }

    int tb0 = tile * 128;

    auto stage = [&](int c) {
        unsigned st = ((unsigned)c) % 3u;
        uint32_t sb = smbase + st * STG_U32 * 4;
#pragma unroll
        for (int e = 0; e < 2; e++) {
            int gidx = tid * 2 + e;                 // 0..511
            int row = gidx >> 5, g32 = gidx & 31;   // 32 granules/row
            uint32_t off = (uint32_t)((g32 * 4 + ((g32 >= 16) ? 4 : 0)) * 4);
            size_t gsrc = ((size_t)(b * 4096 + tb0 + c * CH + row)) * 128 + g32 * 4;
            uint32_t kdst = sb + (uint32_t)(row * KVSTu * 4) + off;
            asm volatile("cp.async.cg.shared.global [%0], [%1], 16;" ::"r"(kdst),
                         "l"(g_kb + gsrc));
            asm volatile("cp.async.cg.shared.global [%0], [%1], 16;" ::"r"(
                             kdst + CH * KVSTu * 4),
                         "l"(g_vb + gsrc));
        }
        asm volatile("cp.async.commit_group;");
    };
    stage(0);
    stage(1);

    int t_d = tid >> 4, s_d = (tid >> 1) & 7, h_d = tid & 1;
    int s_v = tid >> 5, dc = tid & 31;
    uint32_t voff = dc * 4 + ((dc >= 16) ? 4 : 0);
    float av[8];
#pragma unroll
    for (int i2 = 0; i2 < 8; i2++) av[i2] = 0.f;
    float psreg = 0.f;

    for (int c = 0; c < 8; c++) {
        asm volatile("cp.async.wait_group 1;");
        __syncthreads();
        if (c + 2 < 8) stage(c + 2);
        else asm volatile("cp.async.commit_group;");
        const uint32_t* kb = stg + (((unsigned)c) % 3u) * STG_U32;
        const uint32_t* vb = kb + CH * KVSTu;
        {
            const uint32_t* krow = kb + t_d * KVSTu + h_d * 68;
            const float* qrow = qs + s_d * QST + h_d * 132;
            float p = 0.f;
#pragma unroll
            for (int i = 0; i < 16; i++) {
                uint4 kq = *(const uint4*)(krow + i * 4);
                float4 q0 = *(const float4*)(qrow + i * 8);
                float4 q1 = *(const float4*)(qrow + i * 8 + 4);
                float2 f0 = unpackbf(kq.x), f1 = unpackbf(kq.y);
                float2 f2 = unpackbf(kq.z), f3 = unpackbf(kq.w);
                p += f0.x * q0.x + f0.y * q0.y + f1.x * q0.z + f1.y * q0.w;
                p += f2.x * q1.x + f2.y * q1.y + f3.x * q1.z + f3.y * q1.w;
            }
            p += __shfl_xor_sync(0xffffffffu, p, 1);
            if (h_d == 0) dt[t_d * 9 + s_d] = p;
        }
        __syncthreads();
        if (tid < CH) {
            float e[8], m = -1e30f;
#pragma unroll
            for (int s = 0; s < 8; s++) {
                e[s] = dt[tid * 9 + s];
                m = fmaxf(m, e[s]);
            }
            float tot = 0.f;
#pragma unroll
            for (int s = 0; s < 8; s++) {
                e[s] = __expf(e[s] - m);
                tot += e[s];
            }
            float inv = 1.f / tot;
#pragma unroll
            for (int s = 0; s < 8; s++) dt[tid * 9 + s] = e[s] * inv + 1e-8f;
        }
        __syncthreads();
        if (tid < 8) {
#pragma unroll
            for (int t = 0; t < CH; t++) psreg += dt[t * 9 + tid];
        }
#pragma unroll 4
        for (int t = 0; t < CH; t++) {
            float a = dt[t * 9 + s_v];
            uint4 vq = *(const uint4*)(vb + t * KVSTu + voff);
            float2 f0 = unpackbf(vq.x), f1 = unpackbf(vq.y);
            float2 f2 = unpackbf(vq.z), f3 = unpackbf(vq.w);
            av[0] += a * f0.x; av[1] += a * f0.y;
            av[2] += a * f1.x; av[3] += a * f1.y;
            av[4] += a * f2.x; av[5] += a * f2.y;
            av[6] += a * f3.x; av[7] += a * f3.y;
        }
    }
    size_t obase = ((size_t)(b * 32 + tile)) * 2048 + s_v * 256 + dc * 8;
    *(float4*)&g_upd_part[obase] = make_float4(av[0], av[1], av[2], av[3]);
    *(float4*)&g_upd_part[obase + 4] = make_float4(av[4], av[5], av[6], av[7]);
    if (tid < 8) g_psum_part[(b * 32 + tile) * 8 + tid] = psreg;
}

// ---------------- per-iter: finalize upd (deterministic fixed-order reduce) ----------------
__global__ void __launch_bounds__(256) k_upd() {
    int b = blockIdx.x, tid = threadIdx.x;
    __shared__ float ps[8];
    if (tid < 8) {
        float s = 0.f;
        for (int tl = 0; tl < 32; tl++) s += g_psum_part[(b * 32 + tl) * 8 + tid];
        ps[tid] = s;
    }
    __syncthreads();
#pragma unroll
    for (int i = 0; i < 8; i++) {
        float s = 0.f;
        for (int tl = 0; tl < 32; tl++)
            s += g_upd_part[((size_t)(b * 32 + tl)) * 2048 + i * 256 + tid];
        g_upd[b * 2048 + i * 256 + tid] = s / ps[i];
    }
}

// ---------------- per-iter: GRU gate GEMMs (3 blocks per batch) ----------------
__global__ void __launch_bounds__(256) k_gates(const float* __restrict__ wih,
                                               const float* __restrict__ whh,
                                               const float* __restrict__ bih,
                                               const float* __restrict__ bhh) {
    __shared__ float u[2048], pv[2048];
    int b = blockIdx.x, cc = blockIdx.y, tid = threadIdx.x;
    for (int i = tid; i < 2048; i += 256) {
        u[i] = g_upd[b * 2048 + i];
        pv[i] = g_slots[b * 2048 + i];
    }
    __syncthreads();
    int c = cc * 256 + tid;
    float aI[8], aH[8];
    float bi = bih[c], bh = bhh[c];
#pragma unroll
    for (int s = 0; s < 8; s++) { aI[s] = bi; aH[s] = bh; }
    for (int k = 0; k < 256; k++) {
        float wi = wih[k * 768 + c], wh = whh[k * 768 + c];
#pragma unroll
        for (int s = 0; s < 8; s++) {
            aI[s] += u[s * 256 + k] * wi;
            aH[s] += pv[s * 256 + k] * wh;
        }
    }
#pragma unroll
    for (int s = 0; s < 8; s++) {
        g_gi[(b * 8 + s) * 768 + c] = aI[s];
        g_gh[(b * 8 + s) * 768 + c] = aH[s];
    }
}

// ---------------- per-iter: GRU pointwise + residual slot MLP (+ final output) --------
__global__ void __launch_bounds__(256) k_gru2(
    const float* __restrict__ pre_g, const float* __restrict__ pre_b,
    const float* __restrict__ w1, const float* __restrict__ b1,
    const float* __restrict__ w2, const float* __restrict__ b2,
    float* __restrict__ out, int wout) {
    __shared__ float hn[2048], ff[2048], mid[2048];
    int b = blockIdx.x, tid = threadIdx.x;
#pragma unroll
    for (int s = 0; s < 8; s++) {
        size_t gb = (size_t)(b * 8 + s) * 768 + tid;
        float r = 1.f / (1.f + __expf(-(g_gi[gb] + g_gh[gb])));
        float z = 1.f / (1.f + __expf(-(g_gi[gb + 256] + g_gh[gb + 256])));
        float n = tanhf(g_gi[gb + 512] + r * g_gh[gb + 512]);
        hn[s * 256 + tid] = (1.f - z) * n + z * g_slots[b * 2048 + s * 256 + tid];
    }
    __syncthreads();
    {
        int w = tid >> 5, lane = tid & 31;
        float vv[8];
        float s1 = 0.f, s2 = 0.f;
#pragma unroll
        for (int uu = 0; uu < 8; uu++) {
            vv[uu] = hn[w * 256 + lane + 32 * uu];
            s1 += vv[uu];
            s2 += vv[uu] * vv[uu];
        }
        s1 = warp_sum(s1);
        s2 = warp_sum(s2);
        float mu = s1 * (1.0f / 256.0f);
        float rsd = rsqrtf(s2 * (1.0f / 256.0f) - mu * mu + 1e-5f);
#pragma unroll
        for (int uu = 0; uu < 8; uu++) {
            int d = lane + 32 * uu;
            ff[w * 256 + d] = (vv[uu] - mu) * rsd * pre_g[d] + pre_b[d];
        }
    }
    __syncthreads();
    {
        float acc[8];
        float bb = b1[tid];
#pragma unroll
        for (int s = 0; s < 8; s++) acc[s] = bb;
        for (int k = 0; k < 256; k++) {
            float wv = w1[k * 256 + tid];
#pragma unroll
            for (int s = 0; s < 8; s++) acc[s] += ff[s * 256 + k] * wv;
        }
#pragma unroll
        for (int s = 0; s < 8; s++) mid[s * 256 + tid] = fmaxf(acc[s], 0.f);
    }
    __syncthreads();
    {
        float acc[8];
        float bb = b2[tid];
#pragma unroll
        for (int s = 0; s < 8; s++) acc[s] = bb;
        for (int k = 0; k < 256; k++) {
            float wv = w2[k * 256 + tid];
#pragma unroll
            for (int s = 0; s < 8; s++) acc[s] += mid[s * 256 + k] * wv;
        }
#pragma unroll
        for (int s = 0; s < 8; s++) {
            float res = hn[s * 256 + tid] + fmaxf(acc[s], 0.f);
            g_slots[b * 2048 + s * 256 + tid] = res;
            if (wout) out[b * 2048 + s * 256 + tid] = res;
        }
    }
}

// ---------------- host launcher ----------------
extern "C" void kernel_launch(void* const* d_in, const int* in_sizes, int n_in,
                              void* d_out, int out_size) {
    const float* x          = (const float*)d_in[0];
    const float* eps_noise  = (const float*)d_in[1];
    const float* pos_w      = (const float*)d_in[2];
    const float* pos_b      = (const float*)d_in[3];
    const float* enc_g      = (const float*)d_in[4];
    const float* enc_b      = (const float*)d_in[5];
    const float* fm_w1      = (const float*)d_in[6];
    const float* fm_b1      = (const float*)d_in[7];
    const float* fm_w2      = (const float*)d_in[8];
    const float* fm_b2      = (const float*)d_in[9];
    const float* in_g       = (const float*)d_in[10];
    const float* in_b       = (const float*)d_in[11];
    const float* q_w        = (const float*)d_in[12];
    const float* q_b        = (const float*)d_in[13];
    const float* k_w        = (const float*)d_in[14];
    const float* k_b        = (const float*)d_in[15];
    const float* v_w        = (const float*)d_in[16];
    const float* v_b        = (const float*)d_in[17];
    const float* gru_wih    = (const float*)d_in[18];
    const float* gru_whh    = (const float*)d_in[19];
    const float* gru_bih    = (const float*)d_in[20];
    const float* gru_bhh    = (const float*)d_in[21];
    const float* pre_g      = (const float*)d_in[22];
    const float* pre_b      = (const float*)d_in[23];
    const float* st_w1      = (const float*)d_in[24];
    const float* st_b1      = (const float*)d_in[25];
    const float* st_w2      = (const float*)d_in[26];
    const float* st_b2      = (const float*)d_in[27];
    const float* slot_g     = (const float*)d_in[28];
    const float* slot_b     = (const float*)d_in[29];
    const float* slots_loc  = (const float*)d_in[30];
    const float* slots_lsc  = (const float*)d_in[31];

    const int ENC_SMEM = ENC_SMEM_MAX;       // 207872 (covers both encoder variants)
    const int ATTN_SMEM = ATTN_SMEM_BYTES;   // 61248

    cudaFuncSetAttribute(k_encoder, cudaFuncAttributeMaxDynamicSharedMemorySize, ENC_SMEM);
    cudaFuncSetAttribute(k_attn, cudaFuncAttributeMaxDynamicSharedMemorySize, ATTN_SMEM);

    // launch order keeps k_encoder as the 4th launch (ncu captures launch #4)
    k_stats<<<dim3(32, 64), 256>>>(x, pos_w, pos_b);
    k_stats2<<<32, 64>>>();
    k_cvtW2<<<2176, 256>>>(fm_w1, fm_w2, k_w, v_w, enc_g, enc_b);
    k_encoder<<<dim3(32, 32), 512, ENC_SMEM>>>(x, pos_w, pos_b, fm_b1, fm_b2, in_g, in_b,
                                               k_b, v_b);
    k_init<<<32, 256>>>(eps_noise, slots_loc, slots_lsc);
    for (int it = 0; it < 3; it++) {
        k_q<<<32, 256>>>(q_w, q_b, slot_g, slot_b);
        k_attn<<<dim3(32, 32), 256, ATTN_SMEM>>>();
        k_upd<<<32, 256>>>();
        k_gates<<<dim3(32, 3), 256>>>(gru_wih, gru_whh, gru_bih, gru_bhh);
        k_gru2<<<32, 256>>>(pre_g, pre_b, st_w1, st_b1, st_w2, st_b2,
                            (float*)d_out, it == 2 ? 1 : 0);
    }
}